// round 13
// baseline (speedup 1.0000x reference)
#include <cuda_runtime.h>
#include <cuda_fp16.h>
#include <cstdint>
#include <math.h>

#define Bb     16
#define Hh     56
#define Wd     56
#define Nn     3136
#define Dd     256
#define HEADS  8
#define HD     32
#define WIN    7
#define WIN2   49
#define NWH    8
#define NW     64
#define DISP   3
#define FF     1024
#define CPBH   512
#define EPSLN  1e-5f
#define MROWS  50176   // B * N
#define MTILES 196     // MROWS / 256

// ================= PTX helpers =================
__device__ __forceinline__ uint32_t smem_to_u32(const void* p) {
    uint32_t a;
    asm("{ .reg .u64 t; cvta.to.shared.u64 t, %1; cvt.u32.u64 %0, t; }" : "=r"(a) : "l"(p));
    return a;
}
#define CP_ASYNC_CG(dst, src) \
    asm volatile("cp.async.cg.shared.global [%0], [%1], 16;" :: "r"(dst), "l"(src))
#define CP_ASYNC_COMMIT() asm volatile("cp.async.commit_group;" ::: "memory")
#define CP_ASYNC_WAIT(n)  asm volatile("cp.async.wait_group %0;" :: "n"(n) : "memory")

__device__ __forceinline__ void ldsm_x4(uint32_t* r, uint32_t addr) {
    asm volatile("ldmatrix.sync.aligned.m8n8.x4.shared.b16 {%0,%1,%2,%3}, [%4];"
        : "=r"(r[0]), "=r"(r[1]), "=r"(r[2]), "=r"(r[3]) : "r"(addr));
}
__device__ __forceinline__ void mma_f16(float* c, const uint32_t* a, const uint32_t* b) {
    asm volatile("mma.sync.aligned.m16n8k16.row.col.f32.f16.f16.f32 "
        "{%0,%1,%2,%3},{%4,%5,%6,%7},{%8,%9},{%0,%1,%2,%3};"
        : "+f"(c[0]), "+f"(c[1]), "+f"(c[2]), "+f"(c[3])
        : "r"(a[0]), "r"(a[1]), "r"(a[2]), "r"(a[3]), "r"(b[0]), "r"(b[1]));
}

// ================= device scratch =================
__device__ float  g_xm  [MROWS * Dd];
__device__ __half g_xmh [MROWS * Dd];
__device__ __half g_qkv [MROWS * 3 * Dd];
__device__ __half g_ath [MROWS * Dd];
__device__ __half g_ffh [MROWS * FF];
__device__ __half g_tmp [MROWS * Dd];
__device__ float  g_cpb [HEADS * WIN2 * WIN2];
// transposed fp16 weights, per layer:
// [0) qkvT 768x256 | 196608) owT 256x256 | 262144) fw1T 1024x256 | 524288) fw2T 256x1024
#define WLSTRIDE 786432
__device__ __half g_wth [2 * WLSTRIDE];

// ================= small helpers =================
__device__ __forceinline__ uint32_t pack_h2(float a, float b) {
    __half2 h = __floats2half2_rn(a, b);
    return *(uint32_t*)&h;
}

// ================= add SPE =================
__global__ void add_spe_kernel(const float* __restrict__ x, const float* __restrict__ spe,
                               float* __restrict__ xm, __half* __restrict__ xh, int n4) {
    int i = blockIdx.x * blockDim.x + threadIdx.x;
    if (i < n4) {
        float4 a = ((const float4*)x)[i];
        float4 b = ((const float4*)spe)[i];
        a.x += b.x; a.y += b.y; a.z += b.z; a.w += b.w;
        ((float4*)xm)[i] = a;
        uint2 h;
        h.x = pack_h2(a.x, a.y);
        h.y = pack_h2(a.z, a.w);
        ((uint2*)xh)[i] = h;
    }
}

// ================= weight transpose + fp16 round: W[K,N] -> T[N,K], z = layer =================
__global__ void wtconv_kernel(const float* __restrict__ W, __half* __restrict__ Th,
                              int K, int N, size_t wstride, size_t tstride) {
    W  += (size_t)blockIdx.z * wstride;
    Th += (size_t)blockIdx.z * tstride;
    __shared__ float t[32][33];
    int bn = blockIdx.x * 32, bk = blockIdx.y * 32;
    int tx = threadIdx.x, ty = threadIdx.y;
    #pragma unroll
    for (int j = 0; j < 32; j += 8)
        t[ty + j][tx] = W[(size_t)(bk + ty + j) * N + bn + tx];
    __syncthreads();
    #pragma unroll
    for (int j = 0; j < 32; j += 8) {
        Th[(size_t)(bn + ty + j) * K + bk + tx] = __float2half_rn(t[tx][ty + j]);
    }
}

// ================= CPB MLP =================
__global__ void cpb_kernel(const float* __restrict__ cw1, const float* __restrict__ cb1,
                           const float* __restrict__ cw2, const float* __restrict__ cb2,
                           float* __restrict__ cpb) {
    int p = blockIdx.x;
    int i = p / WIN2, j = p % WIN2;
    float dy = (float)(j / WIN - i / WIN);
    float dx = (float)(j % WIN - i % WIN);
    float r0 = ((dy > 0.f) - (dy < 0.f)) * log1pf(fabsf(dy));
    float r1 = ((dx > 0.f) - (dx < 0.f)) * log1pf(fabsf(dx));
    int tid = threadIdx.x;
    int c0 = tid, c1 = tid + 256;
    float h0 = fmaxf(r0 * cw1[c0] + r1 * cw1[CPBH + c0] + cb1[c0], 0.f);
    float h1 = fmaxf(r0 * cw1[c1] + r1 * cw1[CPBH + c1] + cb1[c1], 0.f);
    __shared__ float red[256];
    for (int h = 0; h < HEADS; h++) {
        red[tid] = h0 * cw2[c0 * HEADS + h] + h1 * cw2[c1 * HEADS + h];
        __syncthreads();
        for (int s = 128; s > 0; s >>= 1) {
            if (tid < s) red[tid] += red[tid + s];
            __syncthreads();
        }
        if (tid == 0) cpb[h * (WIN2 * WIN2) + p] = red[0] + cb2[h];
        __syncthreads();
    }
}

// ================= shared epilogue =================
template<int ACT, int OUTMODE>
__device__ __forceinline__ void gemm_epilogue(
    float acc[4][8][4], int bm, int bn, int warpM, int warpN, int lane,
    const float* __restrict__ bias, float* __restrict__ Cf,
    __half* __restrict__ Ch, int Ntot) {
    const int g = lane >> 2, q = lane & 3;
    #pragma unroll
    for (int m = 0; m < 4; m++) {
        #pragma unroll
        for (int n = 0; n < 8; n++) {
            int col = bn + warpN * 64 + n * 8 + 2 * q;
            float b0 = bias ? bias[col] : 0.f;
            float b1 = bias ? bias[col + 1] : 0.f;
            #pragma unroll
            for (int hrow = 0; hrow < 2; hrow++) {
                int row = bm + warpM * 64 + m * 16 + g + hrow * 8;
                float v0 = acc[m][n][hrow * 2 + 0] + b0;
                float v1 = acc[m][n][hrow * 2 + 1] + b1;
                if (ACT == 1) {
                    v0 = v0 * 0.5f * (1.f + erff(v0 * 0.7071067811865476f));
                    v1 = v1 * 0.5f * (1.f + erff(v1 * 0.7071067811865476f));
                }
                if (OUTMODE == 0) {
                    *(float2*)(Cf + (size_t)row * Ntot + col) = make_float2(v0, v1);
                } else {
                    *(uint32_t*)(Ch + (size_t)row * Ntot + col) = pack_h2(v0, v1);
                }
            }
        }
    }
}

// ================= persistent-B HMMA GEMM, K = 256 fixed, pure fp16 =================
#define SAS      40
#define PA_STAGE 20480
#define PSTAGES  4
#define PB_STRIDE 264
#define PB_BYTES (128 * PB_STRIDE * 2)
#define PGEMM_SMEM (PB_BYTES + PSTAGES * PA_STAGE)  // 149504

template<int ACT, bool GATHER, int OUTMODE>
__global__ void __launch_bounds__(256, 1)
hgemm_persist_kernel(const __half* __restrict__ Ah, const __half* __restrict__ Bth,
                     const float* __restrict__ bias, float* __restrict__ Cf,
                     __half* __restrict__ Ch, int Ntot, int G) {
    extern __shared__ char smem_raw[];
    const uint32_t sB = smem_to_u32(smem_raw);
    const uint32_t sA = sB + PB_BYTES;
    const int tid  = threadIdx.x;
    const int lane = tid & 31, wid = tid >> 5;
    const int warpM = wid >> 1, warpN = wid & 1;
    const int bn = blockIdx.x * 128;
    const int g  = blockIdx.y;

    #pragma unroll
    for (int it = 0; it < 16; it++) {
        int idx = tid + it * 256;
        int n = idx >> 5, q = idx & 31;
        CP_ASYNC_CG(sB + (uint32_t)(n * (PB_STRIDE * 2) + q * 16),
                    Bth + (size_t)(bn + n) * 256 + q * 8);
    }
    CP_ASYNC_COMMIT();

    int arow_s[4], acol_s[4];
    uint32_t aoff[4];
    #pragma unroll
    for (int l = 0; l < 4; l++) {
        int c = tid + l * 256;
        int r = c >> 2, q = c & 3;
        arow_s[l] = r; acol_s[l] = q * 8;
        aoff[l] = (uint32_t)(r * (SAS * 2) + q * 16);
    }

    const int ntl = (MTILES - 1 - g) / G + 1;
    const int total_cc = ntl * 8;

    auto issue = [&](int cc) {
        int tile = cc >> 3, c = cc & 7;
        int bm = (g + tile * G) * 256;
        uint32_t stg = sA + (uint32_t)(cc & 3) * PA_STAGE;
        int kt = c << 5;
        #pragma unroll
        for (int l = 0; l < 4; l++) {
            int gm = bm + arow_s[l];
            if (GATHER) {
                int b = gm / Nn, rem = gm - b * Nn;
                int h = rem / Wd, w = rem - h * Wd;
                h = (h + DISP) % Hh; w = (w + DISP) % Wd;
                gm = b * Nn + h * Wd + w;
            }
            CP_ASYNC_CG(stg + aoff[l], Ah + (size_t)gm * 256 + kt + acol_s[l]);
        }
    };

    float acc[4][8][4];
    #pragma unroll
    for (int m = 0; m < 4; m++)
        #pragma unroll
        for (int n = 0; n < 8; n++)
            #pragma unroll
            for (int e = 0; e < 4; e++) acc[m][n][e] = 0.f;

    const int arow  = (lane & 15);
    const int ahalf = (lane >> 4);
    const int bidx  = lane & 7;
    const int bkh   = (lane >> 3) & 1;
    const int bsub  = lane >> 4;

    issue(0); CP_ASYNC_COMMIT();
    if (total_cc > 1) issue(1);
    CP_ASYNC_COMMIT();
    if (total_cc > 2) issue(2);
    CP_ASYNC_COMMIT();

    for (int cc = 0; cc < total_cc; cc++) {
        CP_ASYNC_WAIT(2);
        __syncthreads();
        if (cc + 3 < total_cc) issue(cc + 3);
        CP_ASYNC_COMMIT();

        uint32_t stg = sA + (uint32_t)(cc & 3) * PA_STAGE;
        const int c = cc & 7;
        #pragma unroll
        for (int ks = 0; ks < 2; ks++) {
            const int kg = c * 2 + ks;
            uint32_t ah[4][4], bh[8][2];
            #pragma unroll
            for (int m = 0; m < 4; m++) {
                uint32_t off = (uint32_t)((warpM * 64 + m * 16 + arow) * (SAS * 2)
                                          + (ks * 16 + ahalf * 8) * 2);
                ldsm_x4(ah[m], stg + off);
            }
            #pragma unroll
            for (int pr = 0; pr < 4; pr++) {
                uint32_t off = (uint32_t)((warpN * 64 + pr * 16 + bsub * 8 + bidx) * (PB_STRIDE * 2)
                                          + (kg * 16 + bkh * 8) * 2);
                uint32_t t[4];
                ldsm_x4(t, sB + off);
                bh[pr * 2][0] = t[0]; bh[pr * 2][1] = t[1];
                bh[pr * 2 + 1][0] = t[2]; bh[pr * 2 + 1][1] = t[3];
            }
            #pragma unroll
            for (int m = 0; m < 4; m++)
                #pragma unroll
                for (int n = 0; n < 8; n++) mma_f16(acc[m][n], ah[m], bh[n]);
        }

        if (c == 7) {
            int bm = (g + (cc >> 3) * G) * 256;
            gemm_epilogue<ACT, OUTMODE>(acc, bm, bn, warpM, warpN, lane,
                                        bias, Cf, Ch, Ntot);
            #pragma unroll
            for (int m = 0; m < 4; m++)
                #pragma unroll
                for (int n = 0; n < 8; n++)
                    #pragma unroll
                    for (int e = 0; e < 4; e++) acc[m][n][e] = 0.f;
        }
    }
}

// ================= streaming HMMA GEMM (K=1024 ffn2), pure fp16 =================
#define AH_OFF   0
#define BH_OFF   20480
#define STAGE_B  30720
#define GEMM_SMEM (4 * STAGE_B)

template<int ACT, int OUTMODE>
__global__ void __launch_bounds__(256, 1)
hgemm_kernel(const __half* __restrict__ Ah, const __half* __restrict__ Bth,
             const float* __restrict__ bias, float* __restrict__ Cf,
             __half* __restrict__ Ch, int Ntot, int K) {
    extern __shared__ char smem_raw[];
    const uint32_t sbase = smem_to_u32(smem_raw);
    const int tid  = threadIdx.x;
    const int lane = tid & 31, wid = tid >> 5;
    const int warpM = wid >> 1, warpN = wid & 1;
    const int bm = blockIdx.y * 256, bn = blockIdx.x * 128;

    const __half *pAh[4], *pBh[2];
    uint32_t aoff[4], boff[2];
    #pragma unroll
    for (int l = 0; l < 4; l++) {
        int c = tid + l * 256;
        int r = c >> 2, q = c & 3;
        pAh[l] = Ah + (size_t)(bm + r) * K + q * 8;
        aoff[l] = (uint32_t)(r * (SAS * 2) + q * 16);
    }
    #pragma unroll
    for (int l = 0; l < 2; l++) {
        int c = tid + l * 256;
        int r = c >> 2, q = c & 3;
        pBh[l] = Bth + (size_t)(bn + r) * K + q * 8;
        boff[l] = (uint32_t)(r * (SAS * 2) + q * 16);
    }

    float acc[4][8][4];
    #pragma unroll
    for (int m = 0; m < 4; m++)
        #pragma unroll
        for (int n = 0; n < 8; n++)
            #pragma unroll
            for (int e = 0; e < 4; e++) acc[m][n][e] = 0.f;

    const int nch = K >> 5;

    auto load_stage = [&](int c) {
        uint32_t stg = sbase + (uint32_t)(c & 3) * STAGE_B;
        int kt = c << 5;
        #pragma unroll
        for (int l = 0; l < 4; l++)
            CP_ASYNC_CG(stg + AH_OFF + aoff[l], pAh[l] + kt);
        #pragma unroll
        for (int l = 0; l < 2; l++)
            CP_ASYNC_CG(stg + BH_OFF + boff[l], pBh[l] + kt);
    };

    const int arow  = (lane & 15);
    const int ahalf = (lane >> 4);
    const int bidx  = lane & 7;
    const int bkh   = (lane >> 3) & 1;
    const int bsub  = lane >> 4;

    load_stage(0); CP_ASYNC_COMMIT();
    if (nch > 1) load_stage(1);
    CP_ASYNC_COMMIT();
    if (nch > 2) load_stage(2);
    CP_ASYNC_COMMIT();

    for (int c = 0; c < nch; c++) {
        CP_ASYNC_WAIT(2);
        __syncthreads();
        if (c + 3 < nch) load_stage(c + 3);
        CP_ASYNC_COMMIT();

        uint32_t stg = sbase + (uint32_t)(c & 3) * STAGE_B;
        #pragma unroll
        for (int ks = 0; ks < 2; ks++) {
            uint32_t ah[4][4], bh[8][2];
            #pragma unroll
            for (int m = 0; m < 4; m++) {
                uint32_t off = (uint32_t)((warpM * 64 + m * 16 + arow) * (SAS * 2)
                                          + (ks * 16 + ahalf * 8) * 2);
                ldsm_x4(ah[m], stg + AH_OFF + off);
            }
            #pragma unroll
            for (int pr = 0; pr < 4; pr++) {
                uint32_t off = (uint32_t)((warpN * 64 + pr * 16 + bsub * 8 + bidx) * (SAS * 2)
                                          + (ks * 16 + bkh * 8) * 2);
                uint32_t t[4];
                ldsm_x4(t, stg + BH_OFF + off);
                bh[pr * 2][0] = t[0]; bh[pr * 2][1] = t[1];
                bh[pr * 2 + 1][0] = t[2]; bh[pr * 2 + 1][1] = t[3];
            }
            #pragma unroll
            for (int m = 0; m < 4; m++)
                #pragma unroll
                for (int n = 0; n < 8; n++) mma_f16(acc[m][n], ah[m], bh[n]);
        }
    }

    gemm_epilogue<ACT, OUTMODE>(acc, bm, bn, warpM, warpN, lane, bias, Cf, Ch, Ntot);
}

// ================= window attention (fp16 smem tiles, 8B-aligned stride) =================
#define QS 36
#define DS 52
__global__ void __launch_bounds__(256)
attn_kernel(const __half* __restrict__ qkv, const float* __restrict__ tau,
            const float* __restrict__ cpb, __half* __restrict__ outh, int shifted) {
    __shared__ __half sq[64 * QS];
    __shared__ __half sk[64 * QS];
    __shared__ __half sv[49 * QS];
    __shared__ float  sd[64 * DS];

    const int wi   = blockIdx.x;
    const int head = blockIdx.y;
    const int b    = blockIdx.z;
    const int wh = wi >> 3, ww = wi & 7;
    const int tid = threadIdx.x;

    // vectorized load: 49 rows x 3 tensors x 4 uint4-chunks (8 halves), stored verbatim
    for (int e = tid; e < WIN2 * 12; e += 256) {
        int t = e / (WIN2 * 4);
        int rem = e - t * (WIN2 * 4);
        int r = rem >> 2, c = rem & 3;
        int i = r / WIN, j = r % WIN;
        int m = b * Nn + (wh * WIN + i) * Wd + (ww * WIN + j);
        uint4 u = *(const uint4*)(qkv + (size_t)m * 768 + t * 256 + head * HD + c * 8);
        __half* dst = (t == 0 ? sq : (t == 1 ? sk : sv)) + r * QS + c * 8;
        *(uint2*)(dst)     = make_uint2(u.x, u.y);
        *(uint2*)(dst + 4) = make_uint2(u.z, u.w);
    }
    // zero-pad rows 49..63 of q,k
    for (int e = tid; e < 15 * 16; e += 256) {
        int r = WIN2 + (e >> 4), d = (e & 15) * 2;
        *(uint32_t*)(sq + r * QS + d) = 0u;
        *(uint32_t*)(sk + r * QS + d) = 0u;
    }
    __syncthreads();

    // l2-normalize rows of q,k (fp32 math, store back fp16)
    for (int t = tid; t < 2 * WIN2; t += 256) {
        __half* row = (t < WIN2) ? (sq + t * QS) : (sk + (t - WIN2) * QS);
        float s = 0.f;
        #pragma unroll
        for (int d = 0; d < HD; d += 2) {
            float2 v = __half22float2(*(__half2*)(row + d));
            s += v.x * v.x + v.y * v.y;
        }
        float inv = 1.f / fmaxf(sqrtf(s), 1e-12f);
        #pragma unroll
        for (int d = 0; d < HD; d += 2) {
            float2 v = __half22float2(*(__half2*)(row + d));
            *(uint32_t*)(row + d) = pack_h2(v.x * inv, v.y * inv);
        }
    }
    __syncthreads();

    const float tscale = 1.f / fmaxf(tau[head], 0.01f);
    const int tx = tid & 15, ty = tid >> 4;

    float acc[4][4];
    #pragma unroll
    for (int u = 0; u < 4; u++)
        #pragma unroll
        for (int v = 0; v < 4; v++) acc[u][v] = 0.f;
    #pragma unroll
    for (int kk = 0; kk < HD; kk += 2) {
        float2 a2[4], b2[4];
        #pragma unroll
        for (int u = 0; u < 4; u++)
            a2[u] = __half22float2(*(__half2*)&sq[(ty + u * 16) * QS + kk]);
        #pragma unroll
        for (int v = 0; v < 4; v++)
            b2[v] = __half22float2(*(__half2*)&sk[(tx + v * 16) * QS + kk]);
        #pragma unroll
        for (int u = 0; u < 4; u++)
            #pragma unroll
            for (int v = 0; v < 4; v++)
                acc[u][v] += a2[u].x * b2[v].x + a2[u].y * b2[v].y;
    }
    #pragma unroll
    for (int u = 0; u < 4; u++) {
        int i = ty + u * 16;
        if (i >= WIN2) continue;
        #pragma unroll
        for (int v = 0; v < 4; v++) {
            int j = tx + v * 16;
            if (j >= WIN2) continue;
            float val = acc[u][v] * tscale + cpb[head * (WIN2 * WIN2) + i * WIN2 + j];
            if (shifted) {
                if (wh == NWH - 1 && ((i >= 28) != (j >= 28))) val = -1e30f;
                if (ww == NWH - 1 && (((i % WIN) >= 4) != ((j % WIN) >= 4))) val = -1e30f;
            }
            sd[i * DS + j] = val;
        }
    }
    __syncthreads();

    const int lane = tid & 31, wrp = tid >> 5;
    for (int r = wrp; r < WIN2; r += 8) {
        float v0 = sd[r * DS + lane];
        float v1 = (lane + 32 < WIN2) ? sd[r * DS + lane + 32] : -3e38f;
        float mx = fmaxf(v0, v1);
        #pragma unroll
        for (int o = 16; o > 0; o >>= 1) mx = fmaxf(mx, __shfl_xor_sync(~0u, mx, o));
        float e0 = __expf(v0 - mx);
        float e1 = (lane + 32 < WIN2) ? __expf(v1 - mx) : 0.f;
        float s = e0 + e1;
        #pragma unroll
        for (int o = 16; o > 0; o >>= 1) s += __shfl_xor_sync(~0u, s, o);
        float inv = 1.f / s;
        sd[r * DS + lane] = e0 * inv;
        if (lane + 32 < WIN2) sd[r * DS + lane + 32] = e1 * inv;
    }
    __syncthreads();

    float o2[4][2];
    #pragma unroll
    for (int u = 0; u < 4; u++) { o2[u][0] = 0.f; o2[u][1] = 0.f; }
    for (int j = 0; j < 48; j += 2) {
        float2 p2[4];
        #pragma unroll
        for (int u = 0; u < 4; u++) p2[u] = *(float2*)&sd[(ty + u * 16) * DS + j];
        float2 va = __half22float2(*(__half2*)&sv[j * QS + tx * 2]);
        float2 vb = __half22float2(*(__half2*)&sv[(j + 1) * QS + tx * 2]);
        #pragma unroll
        for (int u = 0; u < 4; u++) {
            o2[u][0] += p2[u].x * va.x + p2[u].y * vb.x;
            o2[u][1] += p2[u].x * va.y + p2[u].y * vb.y;
        }
    }
    {
        float2 vc = __half22float2(*(__half2*)&sv[48 * QS + tx * 2]);
        #pragma unroll
        for (int u = 0; u < 4; u++) {
            float p = sd[(ty + u * 16) * DS + 48];
            o2[u][0] += p * vc.x;
            o2[u][1] += p * vc.y;
        }
    }
    #pragma unroll
    for (int u = 0; u < 4; u++) {
        int i = ty + u * 16;
        if (i < WIN2) {
            int ii = i / WIN, jj = i % WIN;
            int m = b * Nn + (wh * WIN + ii) * Wd + (ww * WIN + jj);
            size_t off = (size_t)m * Dd + head * HD + tx * 2;
            *(uint32_t*)(outh + off) = pack_h2(o2[u][0], o2[u][1]);
        }
    }
}

// ================= LN + residual (reads fp16 A) =================
__global__ void ln_residual_kernel(const __half* __restrict__ A, const float* __restrict__ g,
                                   const float* __restrict__ be, float* __restrict__ xm,
                                   __half* __restrict__ xh, int gather) {
    int row = blockIdx.x * 8 + (threadIdx.x >> 5);
    int lane = threadIdx.x & 31;
    int src = row;
    if (gather) {
        int b = row / Nn, rem = row % Nn;
        int h = rem / Wd, w = rem % Wd;
        src = b * Nn + ((h + Hh - DISP) % Hh) * Wd + ((w + Wd - DISP) % Wd);
    }
    uint4 av = ((const uint4*)(A + (size_t)src * Dd))[lane];
    const __half2* hp = (const __half2*)&av;
    float vals[8];
    #pragma unroll
    for (int k = 0; k < 4; k++) {
        float2 f = __half22float2(hp[k]);
        vals[2 * k] = f.x; vals[2 * k + 1] = f.y;
    }
    float s = 0.f, s2 = 0.f;
    #pragma unroll
    for (int k = 0; k < 8; k++) { s += vals[k]; s2 += vals[k] * vals[k]; }
    #pragma unroll
    for (int o = 16; o > 0; o >>= 1) {
        s  += __shfl_xor_sync(~0u, s, o);
        s2 += __shfl_xor_sync(~0u, s2, o);
    }
    float mean = s * (1.f / Dd);
    float var  = s2 * (1.f / Dd) - mean * mean;
    float inv  = rsqrtf(var + EPSLN);

    float4 g0 = ((const float4*)g)[lane * 2],  g1 = ((const float4*)g)[lane * 2 + 1];
    float4 b0 = ((const float4*)be)[lane * 2], b1 = ((const float4*)be)[lane * 2 + 1];
    float4* x4 = (float4*)(xm + (size_t)row * Dd);
    float4 r0 = x4[lane * 2], r1 = x4[lane * 2 + 1];
    r0.x += (vals[0] - mean) * inv * g0.x + b0.x;
    r0.y += (vals[1] - mean) * inv * g0.y + b0.y;
    r0.z += (vals[2] - mean) * inv * g0.z + b0.z;
    r0.w += (vals[3] - mean) * inv * g0.w + b0.w;
    r1.x += (vals[4] - mean) * inv * g1.x + b1.x;
    r1.y += (vals[5] - mean) * inv * g1.y + b1.y;
    r1.z += (vals[6] - mean) * inv * g1.z + b1.z;
    r1.w += (vals[7] - mean) * inv * g1.w + b1.w;
    x4[lane * 2] = r0; x4[lane * 2 + 1] = r1;

    uint2 h;
    size_t e0 = (size_t)row * Dd + lane * 8;
    h.x = pack_h2(r0.x, r0.y); h.y = pack_h2(r0.z, r0.w);
    *(uint2*)(xh + e0) = h;
    h.x = pack_h2(r1.x, r1.y); h.y = pack_h2(r1.z, r1.w);
    *(uint2*)(xh + e0 + 4) = h;
}

// ================= final LN =================
__global__ void ln_final_kernel(const float* __restrict__ A, const float* __restrict__ g,
                                const float* __restrict__ be, float* __restrict__ out) {
    int row = blockIdx.x * 8 + (threadIdx.x >> 5);
    int lane = threadIdx.x & 31;
    const float4* a4 = (const float4*)(A + (size_t)row * Dd);
    float4 v0 = a4[lane], v1 = a4[lane + 32];
    float s  = v0.x + v0.y + v0.z + v0.w + v1.x + v1.y + v1.z + v1.w;
    float s2 = v0.x*v0.x + v0.y*v0.y + v0.z*v0.z + v0.w*v0.w
             + v1.x*v1.x + v1.y*v1.y + v1.z*v1.z + v1.w*v1.w;
    #pragma unroll
    for (int o = 16; o > 0; o >>= 1) {
        s  += __shfl_xor_sync(~0u, s, o);
        s2 += __shfl_xor_sync(~0u, s2, o);
    }
    float mean = s * (1.f / Dd);
    float var  = s2 * (1.f / Dd) - mean * mean;
    float inv  = rsqrtf(var + EPSLN);
    float4 g0 = ((const float4*)g)[lane],  g1 = ((const float4*)g)[lane + 32];
    float4 b0 = ((const float4*)be)[lane], b1 = ((const float4*)be)[lane + 32];
    float4 o0, o1;
    o0.x = (v0.x - mean) * inv * g0.x + b0.x;
    o0.y = (v0.y - mean) * inv * g0.y + b0.y;
    o0.z = (v0.z - mean) * inv * g0.z + b0.z;
    o0.w = (v0.w - mean) * inv * g0.w + b0.w;
    o1.x = (v1.x - mean) * inv * g1.x + b1.x;
    o1.y = (v1.y - mean) * inv * g1.y + b1.y;
    o1.z = (v1.z - mean) * inv * g1.z + b1.z;
    o1.w = (v1.w - mean) * inv * g1.w + b1.w;
    float4* out4 = (float4*)(out + (size_t)row * Dd);
    out4[lane] = o0; out4[lane + 32] = o1;
}

// ================= launch =================
extern "C" void kernel_launch(void* const* d_in, const int* in_sizes, int n_in,
                              void* d_out, int out_size) {
    const float* x    = (const float*)d_in[0];
    const float* spe  = (const float*)d_in[1];
    const float* qkvw = (const float*)d_in[2];
    const float* tau  = (const float*)d_in[3];
    const float* cw1  = (const float*)d_in[4];
    const float* cb1  = (const float*)d_in[5];
    const float* cw2  = (const float*)d_in[6];
    const float* cb2  = (const float*)d_in[7];
    const float* ow   = (const float*)d_in[8];
    const float* ob   = (const float*)d_in[9];
    const float* ln1g = (const float*)d_in[10];
    const float* ln1b = (const float*)d_in[11];
    const float* fw1  = (const float*)d_in[12];
    const float* fb1  = (const float*)d_in[13];
    const float* fw2  = (const float*)d_in[14];
    const float* fb2  = (const float*)d_in[15];
    const float* ln2g = (const float*)d_in[16];
    const float* ln2b = (const float*)d_in[17];
    const float* ng   = (const float*)d_in[18];
    const float* nb   = (const float*)d_in[19];
    float* out = (float*)d_out;

    float *xm, *cpb;
    __half *xmh, *qkv, *ath, *ffh, *tmph, *wth;
    cudaGetSymbolAddress((void**)&xm,   g_xm);
    cudaGetSymbolAddress((void**)&cpb,  g_cpb);
    cudaGetSymbolAddress((void**)&xmh,  g_xmh);
    cudaGetSymbolAddress((void**)&qkv,  g_qkv);
    cudaGetSymbolAddress((void**)&ath,  g_ath);
    cudaGetSymbolAddress((void**)&ffh,  g_ffh);
    cudaGetSymbolAddress((void**)&tmph, g_tmp);
    cudaGetSymbolAddress((void**)&wth,  g_wth);

    cudaFuncSetAttribute(hgemm_persist_kernel<0, false, 1>, cudaFuncAttributeMaxDynamicSharedMemorySize, PGEMM_SMEM);
    cudaFuncSetAttribute(hgemm_persist_kernel<0, true,  1>, cudaFuncAttributeMaxDynamicSharedMemorySize, PGEMM_SMEM);
    cudaFuncSetAttribute(hgemm_persist_kernel<1, false, 1>, cudaFuncAttributeMaxDynamicSharedMemorySize, PGEMM_SMEM);
    cudaFuncSetAttribute(hgemm_kernel<0, 1>, cudaFuncAttributeMaxDynamicSharedMemorySize, GEMM_SMEM);

    // weight transpose + fp16 round, both layers batched via z
    wtconv_kernel<<<dim3(24, 8, 2), dim3(32, 8)>>>(qkvw, wth,          256, 768,
                                                   (size_t)Dd * 768, WLSTRIDE);
    wtconv_kernel<<<dim3(8,  8, 2), dim3(32, 8)>>>(ow,   wth + 196608, 256, 256,
                                                   (size_t)Dd * Dd,  WLSTRIDE);
    wtconv_kernel<<<dim3(32, 8, 2), dim3(32, 8)>>>(fw1,  wth + 262144, 256, 1024,
                                                   (size_t)Dd * FF,  WLSTRIDE);
    wtconv_kernel<<<dim3(8, 32, 2), dim3(32, 8)>>>(fw2,  wth + 524288, 1024, 256,
                                                   (size_t)FF * Dd,  WLSTRIDE);

    // xm = x + spe (+ fp16)
    {
        int n4 = MROWS * Dd / 4;
        add_spe_kernel<<<(n4 + 255) / 256, 256>>>(x, spe, xm, xmh, n4);
    }

    const int lnBlocks = MROWS / 8;
    for (int layer = 0; layer < 2; layer++) {
        int shifted = (layer == 1);
        size_t wo = (size_t)layer * WLSTRIDE;

        cpb_kernel<<<WIN2 * WIN2, 256>>>(cw1 + layer * 2 * CPBH, cb1 + layer * CPBH,
                                         cw2 + layer * CPBH * HEADS, cb2 + layer * HEADS, cpb);

        // qkv = (rolled) xm @ qkv_w -> fp16   (persistent, 6 x 24 = 144 CTAs)
        if (shifted)
            hgemm_persist_kernel<0, true, 1><<<dim3(6, 24), 256, PGEMM_SMEM>>>(
                xmh, wth + wo, nullptr, nullptr, qkv, 768, 24);
        else
            hgemm_persist_kernel<0, false, 1><<<dim3(6, 24), 256, PGEMM_SMEM>>>(
                xmh, wth + wo, nullptr, nullptr, qkv, 768, 24);

        attn_kernel<<<dim3(NW, HEADS, Bb), 256>>>(qkv, tau + layer * HEADS, cpb, ath, shifted);

        // o-proj -> tmp (fp16)   (persistent, 2 x 74 = 148 CTAs)
        hgemm_persist_kernel<0, false, 1><<<dim3(2, 74), 256, PGEMM_SMEM>>>(
            ath, wth + wo + 196608, ob + layer * Dd, nullptr, tmph, 256, 74);

        // xm += LN(oproj) (rolled back if shifted)
        ln_residual_kernel<<<lnBlocks, 256>>>(tmph, ln1g + layer * Dd, ln1b + layer * Dd,
                                              xm, xmh, shifted);

        // ffn1: gelu(xm @ fw1 + fb1) -> fp16   (persistent, 8 x 18 = 144 CTAs)
        hgemm_persist_kernel<1, false, 1><<<dim3(8, 18), 256, PGEMM_SMEM>>>(
            xmh, wth + wo + 262144, fb1 + layer * FF, nullptr, ffh, 1024, 18);

        // ffn2 -> tmp (fp16)   (streaming, K=1024)
        hgemm_kernel<0, 1><<<dim3(2, MROWS / 256), 256, GEMM_SMEM>>>(
            ffh, wth + wo + 524288, fb2 + layer * Dd, nullptr, tmph, 256, 1024);

        // xm += LN(ffn2)
        ln_residual_kernel<<<lnBlocks, 256>>>(tmph, ln2g + layer * Dd, ln2b + layer * Dd,
                                              xm, xmh, 0);
    }

    ln_final_kernel<<<MROWS / 8, 256>>>(xm, ng, nb, out);
}

// round 14
// speedup vs baseline: 1.0510x; 1.0510x over previous
#include <cuda_runtime.h>
#include <cuda_fp16.h>
#include <cstdint>
#include <math.h>

#define Bb     16
#define Hh     56
#define Wd     56
#define Nn     3136
#define Dd     256
#define HEADS  8
#define HD     32
#define WIN    7
#define WIN2   49
#define NWH    8
#define NW     64
#define DISP   3
#define FF     1024
#define CPBH   512
#define EPSLN  1e-5f
#define MROWS  50176   // B * N
#define MTILES 196     // MROWS / 256

// ================= PTX helpers =================
__device__ __forceinline__ uint32_t smem_to_u32(const void* p) {
    uint32_t a;
    asm("{ .reg .u64 t; cvta.to.shared.u64 t, %1; cvt.u32.u64 %0, t; }" : "=r"(a) : "l"(p));
    return a;
}
#define CP_ASYNC_CG(dst, src) \
    asm volatile("cp.async.cg.shared.global [%0], [%1], 16;" :: "r"(dst), "l"(src))
#define CP_ASYNC_COMMIT() asm volatile("cp.async.commit_group;" ::: "memory")
#define CP_ASYNC_WAIT(n)  asm volatile("cp.async.wait_group %0;" :: "n"(n) : "memory")

__device__ __forceinline__ void ldsm_x4(uint32_t* r, uint32_t addr) {
    asm volatile("ldmatrix.sync.aligned.m8n8.x4.shared.b16 {%0,%1,%2,%3}, [%4];"
        : "=r"(r[0]), "=r"(r[1]), "=r"(r[2]), "=r"(r[3]) : "r"(addr));
}
__device__ __forceinline__ void mma_f16(float* c, const uint32_t* a, const uint32_t* b) {
    asm volatile("mma.sync.aligned.m16n8k16.row.col.f32.f16.f16.f32 "
        "{%0,%1,%2,%3},{%4,%5,%6,%7},{%8,%9},{%0,%1,%2,%3};"
        : "+f"(c[0]), "+f"(c[1]), "+f"(c[2]), "+f"(c[3])
        : "r"(a[0]), "r"(a[1]), "r"(a[2]), "r"(a[3]), "r"(b[0]), "r"(b[1]));
}

// ================= device scratch =================
__device__ __half g_xmh [MROWS * Dd];          // fp16 residual stream
__device__ __half g_qkv [MROWS * 3 * Dd];
__device__ __half g_ath [MROWS * Dd];
__device__ __half g_ffh [MROWS * FF];
__device__ __half g_tmp [MROWS * Dd];
__device__ float  g_cpb [HEADS * WIN2 * WIN2];
// transposed fp16 weights, per layer:
// [0) qkvT 768x256 | 196608) owT 256x256 | 262144) fw1T 1024x256 | 524288) fw2T 256x1024
#define WLSTRIDE 786432
__device__ __half g_wth [2 * WLSTRIDE];

// ================= small helpers =================
__device__ __forceinline__ uint32_t pack_h2(float a, float b) {
    __half2 h = __floats2half2_rn(a, b);
    return *(uint32_t*)&h;
}

// ================= add SPE (fp16 out) =================
__global__ void add_spe_kernel(const float* __restrict__ x, const float* __restrict__ spe,
                               __half* __restrict__ xh, int n4) {
    int i = blockIdx.x * blockDim.x + threadIdx.x;
    if (i < n4) {
        float4 a = ((const float4*)x)[i];
        float4 b = ((const float4*)spe)[i];
        uint2 h;
        h.x = pack_h2(a.x + b.x, a.y + b.y);
        h.y = pack_h2(a.z + b.z, a.w + b.w);
        ((uint2*)xh)[i] = h;
    }
}

// ================= weight transpose + fp16 round: W[K,N] -> T[N,K], z = layer =================
__global__ void wtconv_kernel(const float* __restrict__ W, __half* __restrict__ Th,
                              int K, int N, size_t wstride, size_t tstride) {
    W  += (size_t)blockIdx.z * wstride;
    Th += (size_t)blockIdx.z * tstride;
    __shared__ float t[32][33];
    int bn = blockIdx.x * 32, bk = blockIdx.y * 32;
    int tx = threadIdx.x, ty = threadIdx.y;
    #pragma unroll
    for (int j = 0; j < 32; j += 8)
        t[ty + j][tx] = W[(size_t)(bk + ty + j) * N + bn + tx];
    __syncthreads();
    #pragma unroll
    for (int j = 0; j < 32; j += 8) {
        Th[(size_t)(bn + ty + j) * K + bk + tx] = __float2half_rn(t[tx][ty + j]);
    }
}

// ================= CPB MLP =================
__global__ void cpb_kernel(const float* __restrict__ cw1, const float* __restrict__ cb1,
                           const float* __restrict__ cw2, const float* __restrict__ cb2,
                           float* __restrict__ cpb) {
    int p = blockIdx.x;
    int i = p / WIN2, j = p % WIN2;
    float dy = (float)(j / WIN - i / WIN);
    float dx = (float)(j % WIN - i % WIN);
    float r0 = ((dy > 0.f) - (dy < 0.f)) * log1pf(fabsf(dy));
    float r1 = ((dx > 0.f) - (dx < 0.f)) * log1pf(fabsf(dx));
    int tid = threadIdx.x;
    int c0 = tid, c1 = tid + 256;
    float h0 = fmaxf(r0 * cw1[c0] + r1 * cw1[CPBH + c0] + cb1[c0], 0.f);
    float h1 = fmaxf(r0 * cw1[c1] + r1 * cw1[CPBH + c1] + cb1[c1], 0.f);
    __shared__ float red[256];
    for (int h = 0; h < HEADS; h++) {
        red[tid] = h0 * cw2[c0 * HEADS + h] + h1 * cw2[c1 * HEADS + h];
        __syncthreads();
        for (int s = 128; s > 0; s >>= 1) {
            if (tid < s) red[tid] += red[tid + s];
            __syncthreads();
        }
        if (tid == 0) cpb[h * (WIN2 * WIN2) + p] = red[0] + cb2[h];
        __syncthreads();
    }
}

// ================= shared epilogue (fp16 out only) =================
template<int ACT>
__device__ __forceinline__ void gemm_epilogue(
    float acc[4][8][4], int bm, int bn, int warpM, int warpN, int lane,
    const float* __restrict__ bias, __half* __restrict__ Ch, int Ntot) {
    const int g = lane >> 2, q = lane & 3;
    #pragma unroll
    for (int m = 0; m < 4; m++) {
        #pragma unroll
        for (int n = 0; n < 8; n++) {
            int col = bn + warpN * 64 + n * 8 + 2 * q;
            float b0 = bias ? bias[col] : 0.f;
            float b1 = bias ? bias[col + 1] : 0.f;
            #pragma unroll
            for (int hrow = 0; hrow < 2; hrow++) {
                int row = bm + warpM * 64 + m * 16 + g + hrow * 8;
                float v0 = acc[m][n][hrow * 2 + 0] + b0;
                float v1 = acc[m][n][hrow * 2 + 1] + b1;
                if (ACT == 1) {
                    v0 = v0 * 0.5f * (1.f + erff(v0 * 0.7071067811865476f));
                    v1 = v1 * 0.5f * (1.f + erff(v1 * 0.7071067811865476f));
                }
                *(uint32_t*)(Ch + (size_t)row * Ntot + col) = pack_h2(v0, v1);
            }
        }
    }
}

// ================= persistent-B HMMA GEMM, K = 256 fixed, pure fp16 =================
#define SAS      40
#define PA_STAGE 20480
#define PSTAGES  4
#define PB_STRIDE 264
#define PB_BYTES (128 * PB_STRIDE * 2)
#define PGEMM_SMEM (PB_BYTES + PSTAGES * PA_STAGE)  // 149504

template<int ACT, bool GATHER>
__global__ void __launch_bounds__(256, 1)
hgemm_persist_kernel(const __half* __restrict__ Ah, const __half* __restrict__ Bth,
                     const float* __restrict__ bias, __half* __restrict__ Ch,
                     int Ntot, int G) {
    extern __shared__ char smem_raw[];
    const uint32_t sB = smem_to_u32(smem_raw);
    const uint32_t sA = sB + PB_BYTES;
    const int tid  = threadIdx.x;
    const int lane = tid & 31, wid = tid >> 5;
    const int warpM = wid >> 1, warpN = wid & 1;
    const int bn = blockIdx.x * 128;
    const int g  = blockIdx.y;

    #pragma unroll
    for (int it = 0; it < 16; it++) {
        int idx = tid + it * 256;
        int n = idx >> 5, q = idx & 31;
        CP_ASYNC_CG(sB + (uint32_t)(n * (PB_STRIDE * 2) + q * 16),
                    Bth + (size_t)(bn + n) * 256 + q * 8);
    }
    CP_ASYNC_COMMIT();

    int arow_s[4], acol_s[4];
    uint32_t aoff[4];
    #pragma unroll
    for (int l = 0; l < 4; l++) {
        int c = tid + l * 256;
        int r = c >> 2, q = c & 3;
        arow_s[l] = r; acol_s[l] = q * 8;
        aoff[l] = (uint32_t)(r * (SAS * 2) + q * 16);
    }

    const int ntl = (MTILES - 1 - g) / G + 1;
    const int total_cc = ntl * 8;

    auto issue = [&](int cc) {
        int tile = cc >> 3, c = cc & 7;
        int bm = (g + tile * G) * 256;
        uint32_t stg = sA + (uint32_t)(cc & 3) * PA_STAGE;
        int kt = c << 5;
        #pragma unroll
        for (int l = 0; l < 4; l++) {
            int gm = bm + arow_s[l];
            if (GATHER) {
                int b = gm / Nn, rem = gm - b * Nn;
                int h = rem / Wd, w = rem - h * Wd;
                h = (h + DISP) % Hh; w = (w + DISP) % Wd;
                gm = b * Nn + h * Wd + w;
            }
            CP_ASYNC_CG(stg + aoff[l], Ah + (size_t)gm * 256 + kt + acol_s[l]);
        }
    };

    float acc[4][8][4];
    #pragma unroll
    for (int m = 0; m < 4; m++)
        #pragma unroll
        for (int n = 0; n < 8; n++)
            #pragma unroll
            for (int e = 0; e < 4; e++) acc[m][n][e] = 0.f;

    const int arow  = (lane & 15);
    const int ahalf = (lane >> 4);
    const int bidx  = lane & 7;
    const int bkh   = (lane >> 3) & 1;
    const int bsub  = lane >> 4;

    issue(0); CP_ASYNC_COMMIT();
    if (total_cc > 1) issue(1);
    CP_ASYNC_COMMIT();
    if (total_cc > 2) issue(2);
    CP_ASYNC_COMMIT();

    for (int cc = 0; cc < total_cc; cc++) {
        CP_ASYNC_WAIT(2);
        __syncthreads();
        if (cc + 3 < total_cc) issue(cc + 3);
        CP_ASYNC_COMMIT();

        uint32_t stg = sA + (uint32_t)(cc & 3) * PA_STAGE;
        const int c = cc & 7;
        #pragma unroll
        for (int ks = 0; ks < 2; ks++) {
            const int kg = c * 2 + ks;
            uint32_t ah[4][4], bh[8][2];
            #pragma unroll
            for (int m = 0; m < 4; m++) {
                uint32_t off = (uint32_t)((warpM * 64 + m * 16 + arow) * (SAS * 2)
                                          + (ks * 16 + ahalf * 8) * 2);
                ldsm_x4(ah[m], stg + off);
            }
            #pragma unroll
            for (int pr = 0; pr < 4; pr++) {
                uint32_t off = (uint32_t)((warpN * 64 + pr * 16 + bsub * 8 + bidx) * (PB_STRIDE * 2)
                                          + (kg * 16 + bkh * 8) * 2);
                uint32_t t[4];
                ldsm_x4(t, sB + off);
                bh[pr * 2][0] = t[0]; bh[pr * 2][1] = t[1];
                bh[pr * 2 + 1][0] = t[2]; bh[pr * 2 + 1][1] = t[3];
            }
            #pragma unroll
            for (int m = 0; m < 4; m++)
                #pragma unroll
                for (int n = 0; n < 8; n++) mma_f16(acc[m][n], ah[m], bh[n]);
        }

        if (c == 7) {
            int bm = (g + (cc >> 3) * G) * 256;
            gemm_epilogue<ACT>(acc, bm, bn, warpM, warpN, lane, bias, Ch, Ntot);
            #pragma unroll
            for (int m = 0; m < 4; m++)
                #pragma unroll
                for (int n = 0; n < 8; n++)
                    #pragma unroll
                    for (int e = 0; e < 4; e++) acc[m][n][e] = 0.f;
        }
    }
}

// ================= streaming HMMA GEMM (K=1024 ffn2), pure fp16 =================
#define AH_OFF   0
#define BH_OFF   20480
#define STAGE_B  30720
#define GEMM_SMEM (4 * STAGE_B)

template<int ACT>
__global__ void __launch_bounds__(256, 1)
hgemm_kernel(const __half* __restrict__ Ah, const __half* __restrict__ Bth,
             const float* __restrict__ bias, __half* __restrict__ Ch,
             int Ntot, int K) {
    extern __shared__ char smem_raw[];
    const uint32_t sbase = smem_to_u32(smem_raw);
    const int tid  = threadIdx.x;
    const int lane = tid & 31, wid = tid >> 5;
    const int warpM = wid >> 1, warpN = wid & 1;
    const int bm = blockIdx.y * 256, bn = blockIdx.x * 128;

    const __half *pAh[4], *pBh[2];
    uint32_t aoff[4], boff[2];
    #pragma unroll
    for (int l = 0; l < 4; l++) {
        int c = tid + l * 256;
        int r = c >> 2, q = c & 3;
        pAh[l] = Ah + (size_t)(bm + r) * K + q * 8;
        aoff[l] = (uint32_t)(r * (SAS * 2) + q * 16);
    }
    #pragma unroll
    for (int l = 0; l < 2; l++) {
        int c = tid + l * 256;
        int r = c >> 2, q = c & 3;
        pBh[l] = Bth + (size_t)(bn + r) * K + q * 8;
        boff[l] = (uint32_t)(r * (SAS * 2) + q * 16);
    }

    float acc[4][8][4];
    #pragma unroll
    for (int m = 0; m < 4; m++)
        #pragma unroll
        for (int n = 0; n < 8; n++)
            #pragma unroll
            for (int e = 0; e < 4; e++) acc[m][n][e] = 0.f;

    const int nch = K >> 5;

    auto load_stage = [&](int c) {
        uint32_t stg = sbase + (uint32_t)(c & 3) * STAGE_B;
        int kt = c << 5;
        #pragma unroll
        for (int l = 0; l < 4; l++)
            CP_ASYNC_CG(stg + AH_OFF + aoff[l], pAh[l] + kt);
        #pragma unroll
        for (int l = 0; l < 2; l++)
            CP_ASYNC_CG(stg + BH_OFF + boff[l], pBh[l] + kt);
    };

    const int arow  = (lane & 15);
    const int ahalf = (lane >> 4);
    const int bidx  = lane & 7;
    const int bkh   = (lane >> 3) & 1;
    const int bsub  = lane >> 4;

    load_stage(0); CP_ASYNC_COMMIT();
    if (nch > 1) load_stage(1);
    CP_ASYNC_COMMIT();
    if (nch > 2) load_stage(2);
    CP_ASYNC_COMMIT();

    for (int c = 0; c < nch; c++) {
        CP_ASYNC_WAIT(2);
        __syncthreads();
        if (c + 3 < nch) load_stage(c + 3);
        CP_ASYNC_COMMIT();

        uint32_t stg = sbase + (uint32_t)(c & 3) * STAGE_B;
        #pragma unroll
        for (int ks = 0; ks < 2; ks++) {
            uint32_t ah[4][4], bh[8][2];
            #pragma unroll
            for (int m = 0; m < 4; m++) {
                uint32_t off = (uint32_t)((warpM * 64 + m * 16 + arow) * (SAS * 2)
                                          + (ks * 16 + ahalf * 8) * 2);
                ldsm_x4(ah[m], stg + AH_OFF + off);
            }
            #pragma unroll
            for (int pr = 0; pr < 4; pr++) {
                uint32_t off = (uint32_t)((warpN * 64 + pr * 16 + bsub * 8 + bidx) * (SAS * 2)
                                          + (ks * 16 + bkh * 8) * 2);
                uint32_t t[4];
                ldsm_x4(t, stg + BH_OFF + off);
                bh[pr * 2][0] = t[0]; bh[pr * 2][1] = t[1];
                bh[pr * 2 + 1][0] = t[2]; bh[pr * 2 + 1][1] = t[3];
            }
            #pragma unroll
            for (int m = 0; m < 4; m++)
                #pragma unroll
                for (int n = 0; n < 8; n++) mma_f16(acc[m][n], ah[m], bh[n]);
        }
    }

    gemm_epilogue<ACT>(acc, bm, bn, warpM, warpN, lane, bias, Ch, Ntot);
}

// ================= window attention (R11 fp32-smem version, reads fp16 qkv) =================
#define QS 34
#define DS 52
__global__ void __launch_bounds__(256)
attn_kernel(const __half* __restrict__ qkv, const float* __restrict__ tau,
            const float* __restrict__ cpb, __half* __restrict__ outh, int shifted) {
    __shared__ float sq[64 * QS];
    __shared__ float sk[64 * QS];
    __shared__ float sv[49 * QS];
    __shared__ float sd[64 * DS];

    const int wi   = blockIdx.x;
    const int head = blockIdx.y;
    const int b    = blockIdx.z;
    const int wh = wi >> 3, ww = wi & 7;
    const int tid = threadIdx.x;

    // vectorized load: 49 rows x 3 tensors x 4 uint4-chunks (8 halves each)
    for (int e = tid; e < WIN2 * 12; e += 256) {
        int t = e / (WIN2 * 4);
        int rem = e - t * (WIN2 * 4);
        int r = rem >> 2, c = rem & 3;
        int i = r / WIN, j = r % WIN;
        int m = b * Nn + (wh * WIN + i) * Wd + (ww * WIN + j);
        uint4 u = *(const uint4*)(qkv + (size_t)m * 768 + t * 256 + head * HD + c * 8);
        float* dst = (t == 0 ? sq : (t == 1 ? sk : sv)) + r * QS + c * 8;
        const __half2* hp = (const __half2*)&u;
        #pragma unroll
        for (int kk = 0; kk < 4; kk++) {
            float2 f = __half22float2(hp[kk]);
            *(float2*)(dst + kk * 2) = f;
        }
    }
    // zero-pad rows 49..63 of q,k
    for (int e = tid; e < 15 * 32; e += 256) {
        int r = WIN2 + (e >> 5), d = e & 31;
        sq[r * QS + d] = 0.f;
        sk[r * QS + d] = 0.f;
    }
    __syncthreads();

    for (int t = tid; t < 2 * WIN2; t += 256) {
        float* row = (t < WIN2) ? (sq + t * QS) : (sk + (t - WIN2) * QS);
        float s = 0.f;
        #pragma unroll
        for (int d = 0; d < HD; d += 2) {
            float2 v = *(float2*)(row + d);
            s += v.x * v.x + v.y * v.y;
        }
        float inv = 1.f / fmaxf(sqrtf(s), 1e-12f);
        #pragma unroll
        for (int d = 0; d < HD; d += 2) {
            float2 v = *(float2*)(row + d);
            v.x *= inv; v.y *= inv;
            *(float2*)(row + d) = v;
        }
    }
    __syncthreads();

    const float tscale = 1.f / fmaxf(tau[head], 0.01f);
    const int tx = tid & 15, ty = tid >> 4;

    float acc[4][4];
    #pragma unroll
    for (int u = 0; u < 4; u++)
        #pragma unroll
        for (int v = 0; v < 4; v++) acc[u][v] = 0.f;
    #pragma unroll
    for (int kk = 0; kk < HD; kk += 2) {
        float2 a2[4], b2[4];
        #pragma unroll
        for (int u = 0; u < 4; u++) a2[u] = *(float2*)&sq[(ty + u * 16) * QS + kk];
        #pragma unroll
        for (int v = 0; v < 4; v++) b2[v] = *(float2*)&sk[(tx + v * 16) * QS + kk];
        #pragma unroll
        for (int u = 0; u < 4; u++)
            #pragma unroll
            for (int v = 0; v < 4; v++)
                acc[u][v] += a2[u].x * b2[v].x + a2[u].y * b2[v].y;
    }
    #pragma unroll
    for (int u = 0; u < 4; u++) {
        int i = ty + u * 16;
        if (i >= WIN2) continue;
        #pragma unroll
        for (int v = 0; v < 4; v++) {
            int j = tx + v * 16;
            if (j >= WIN2) continue;
            float val = acc[u][v] * tscale + cpb[head * (WIN2 * WIN2) + i * WIN2 + j];
            if (shifted) {
                if (wh == NWH - 1 && ((i >= 28) != (j >= 28))) val = -1e30f;
                if (ww == NWH - 1 && (((i % WIN) >= 4) != ((j % WIN) >= 4))) val = -1e30f;
            }
            sd[i * DS + j] = val;
        }
    }
    __syncthreads();

    const int lane = tid & 31, wrp = tid >> 5;
    for (int r = wrp; r < WIN2; r += 8) {
        float v0 = sd[r * DS + lane];
        float v1 = (lane + 32 < WIN2) ? sd[r * DS + lane + 32] : -3e38f;
        float mx = fmaxf(v0, v1);
        #pragma unroll
        for (int o = 16; o > 0; o >>= 1) mx = fmaxf(mx, __shfl_xor_sync(~0u, mx, o));
        float e0 = __expf(v0 - mx);
        float e1 = (lane + 32 < WIN2) ? __expf(v1 - mx) : 0.f;
        float s = e0 + e1;
        #pragma unroll
        for (int o = 16; o > 0; o >>= 1) s += __shfl_xor_sync(~0u, s, o);
        float inv = 1.f / s;
        sd[r * DS + lane] = e0 * inv;
        if (lane + 32 < WIN2) sd[r * DS + lane + 32] = e1 * inv;
    }
    __syncthreads();

    float o2[4][2];
    #pragma unroll
    for (int u = 0; u < 4; u++) { o2[u][0] = 0.f; o2[u][1] = 0.f; }
    for (int j = 0; j < 48; j += 2) {
        float2 p2[4];
        #pragma unroll
        for (int u = 0; u < 4; u++) p2[u] = *(float2*)&sd[(ty + u * 16) * DS + j];
        float2 va = *(float2*)&sv[j * QS + tx * 2];
        float2 vb = *(float2*)&sv[(j + 1) * QS + tx * 2];
        #pragma unroll
        for (int u = 0; u < 4; u++) {
            o2[u][0] += p2[u].x * va.x + p2[u].y * vb.x;
            o2[u][1] += p2[u].x * va.y + p2[u].y * vb.y;
        }
    }
    {
        float2 vc = *(float2*)&sv[48 * QS + tx * 2];
        #pragma unroll
        for (int u = 0; u < 4; u++) {
            float p = sd[(ty + u * 16) * DS + 48];
            o2[u][0] += p * vc.x;
            o2[u][1] += p * vc.y;
        }
    }
    #pragma unroll
    for (int u = 0; u < 4; u++) {
        int i = ty + u * 16;
        if (i < WIN2) {
            int ii = i / WIN, jj = i % WIN;
            int m = b * Nn + (wh * WIN + ii) * Wd + (ww * WIN + jj);
            size_t off = (size_t)m * Dd + head * HD + tx * 2;
            *(uint32_t*)(outh + off) = pack_h2(o2[u][0], o2[u][1]);
        }
    }
}

// ================= LN + residual (fp16 stream, fp32 math) =================
__global__ void ln_residual_kernel(const __half* __restrict__ A, const float* __restrict__ g,
                                   const float* __restrict__ be, __half* __restrict__ xh,
                                   int gather) {
    int row = blockIdx.x * 8 + (threadIdx.x >> 5);
    int lane = threadIdx.x & 31;
    int src = row;
    if (gather) {
        int b = row / Nn, rem = row % Nn;
        int h = rem / Wd, w = rem % Wd;
        src = b * Nn + ((h + Hh - DISP) % Hh) * Wd + ((w + Wd - DISP) % Wd);
    }
    uint4 av = ((const uint4*)(A + (size_t)src * Dd))[lane];
    const __half2* hp = (const __half2*)&av;
    float vals[8];
    #pragma unroll
    for (int k = 0; k < 4; k++) {
        float2 f = __half22float2(hp[k]);
        vals[2 * k] = f.x; vals[2 * k + 1] = f.y;
    }
    float s = 0.f, s2 = 0.f;
    #pragma unroll
    for (int k = 0; k < 8; k++) { s += vals[k]; s2 += vals[k] * vals[k]; }
    #pragma unroll
    for (int o = 16; o > 0; o >>= 1) {
        s  += __shfl_xor_sync(~0u, s, o);
        s2 += __shfl_xor_sync(~0u, s2, o);
    }
    float mean = s * (1.f / Dd);
    float var  = s2 * (1.f / Dd) - mean * mean;
    float inv  = rsqrtf(var + EPSLN);

    float4 g0 = ((const float4*)g)[lane * 2],  g1 = ((const float4*)g)[lane * 2 + 1];
    float4 b0 = ((const float4*)be)[lane * 2], b1 = ((const float4*)be)[lane * 2 + 1];

    uint4* xp = (uint4*)(xh + (size_t)row * Dd + lane * 8);
    uint4 xv = *xp;
    const __half2* xh2 = (const __half2*)&xv;
    float r[8];
    #pragma unroll
    for (int k = 0; k < 4; k++) {
        float2 f = __half22float2(xh2[k]);
        r[2 * k] = f.x; r[2 * k + 1] = f.y;
    }
    r[0] += (vals[0] - mean) * inv * g0.x + b0.x;
    r[1] += (vals[1] - mean) * inv * g0.y + b0.y;
    r[2] += (vals[2] - mean) * inv * g0.z + b0.z;
    r[3] += (vals[3] - mean) * inv * g0.w + b0.w;
    r[4] += (vals[4] - mean) * inv * g1.x + b1.x;
    r[5] += (vals[5] - mean) * inv * g1.y + b1.y;
    r[6] += (vals[6] - mean) * inv * g1.z + b1.z;
    r[7] += (vals[7] - mean) * inv * g1.w + b1.w;
    uint4 ov;
    ov.x = pack_h2(r[0], r[1]); ov.y = pack_h2(r[2], r[3]);
    ov.z = pack_h2(r[4], r[5]); ov.w = pack_h2(r[6], r[7]);
    *xp = ov;
}

// ================= final LN (reads fp16 stream) =================
__global__ void ln_final_kernel(const __half* __restrict__ A, const float* __restrict__ g,
                                const float* __restrict__ be, float* __restrict__ out) {
    int row = blockIdx.x * 8 + (threadIdx.x >> 5);
    int lane = threadIdx.x & 31;
    uint4 av = ((const uint4*)(A + (size_t)row * Dd))[lane];
    const __half2* hp = (const __half2*)&av;
    float vals[8];
    #pragma unroll
    for (int k = 0; k < 4; k++) {
        float2 f = __half22float2(hp[k]);
        vals[2 * k] = f.x; vals[2 * k + 1] = f.y;
    }
    float s = 0.f, s2 = 0.f;
    #pragma unroll
    for (int k = 0; k < 8; k++) { s += vals[k]; s2 += vals[k] * vals[k]; }
    #pragma unroll
    for (int o = 16; o > 0; o >>= 1) {
        s  += __shfl_xor_sync(~0u, s, o);
        s2 += __shfl_xor_sync(~0u, s2, o);
    }
    float mean = s * (1.f / Dd);
    float var  = s2 * (1.f / Dd) - mean * mean;
    float inv  = rsqrtf(var + EPSLN);
    float4 g0 = ((const float4*)g)[lane * 2],  g1 = ((const float4*)g)[lane * 2 + 1];
    float4 b0 = ((const float4*)be)[lane * 2], b1 = ((const float4*)be)[lane * 2 + 1];
    float4 o0, o1;
    o0.x = (vals[0] - mean) * inv * g0.x + b0.x;
    o0.y = (vals[1] - mean) * inv * g0.y + b0.y;
    o0.z = (vals[2] - mean) * inv * g0.z + b0.z;
    o0.w = (vals[3] - mean) * inv * g0.w + b0.w;
    o1.x = (vals[4] - mean) * inv * g1.x + b1.x;
    o1.y = (vals[5] - mean) * inv * g1.y + b1.y;
    o1.z = (vals[6] - mean) * inv * g1.z + b1.z;
    o1.w = (vals[7] - mean) * inv * g1.w + b1.w;
    float4* out4 = (float4*)(out + (size_t)row * Dd + lane * 8);
    out4[0] = o0; out4[1] = o1;
}

// ================= launch =================
extern "C" void kernel_launch(void* const* d_in, const int* in_sizes, int n_in,
                              void* d_out, int out_size) {
    const float* x    = (const float*)d_in[0];
    const float* spe  = (const float*)d_in[1];
    const float* qkvw = (const float*)d_in[2];
    const float* tau  = (const float*)d_in[3];
    const float* cw1  = (const float*)d_in[4];
    const float* cb1  = (const float*)d_in[5];
    const float* cw2  = (const float*)d_in[6];
    const float* cb2  = (const float*)d_in[7];
    const float* ow   = (const float*)d_in[8];
    const float* ob   = (const float*)d_in[9];
    const float* ln1g = (const float*)d_in[10];
    const float* ln1b = (const float*)d_in[11];
    const float* fw1  = (const float*)d_in[12];
    const float* fb1  = (const float*)d_in[13];
    const float* fw2  = (const float*)d_in[14];
    const float* fb2  = (const float*)d_in[15];
    const float* ln2g = (const float*)d_in[16];
    const float* ln2b = (const float*)d_in[17];
    const float* ng   = (const float*)d_in[18];
    const float* nb   = (const float*)d_in[19];
    float* out = (float*)d_out;

    float *cpb;
    __half *xmh, *qkv, *ath, *ffh, *tmph, *wth;
    cudaGetSymbolAddress((void**)&cpb,  g_cpb);
    cudaGetSymbolAddress((void**)&xmh,  g_xmh);
    cudaGetSymbolAddress((void**)&qkv,  g_qkv);
    cudaGetSymbolAddress((void**)&ath,  g_ath);
    cudaGetSymbolAddress((void**)&ffh,  g_ffh);
    cudaGetSymbolAddress((void**)&tmph, g_tmp);
    cudaGetSymbolAddress((void**)&wth,  g_wth);

    cudaFuncSetAttribute(hgemm_persist_kernel<0, false>, cudaFuncAttributeMaxDynamicSharedMemorySize, PGEMM_SMEM);
    cudaFuncSetAttribute(hgemm_persist_kernel<0, true>,  cudaFuncAttributeMaxDynamicSharedMemorySize, PGEMM_SMEM);
    cudaFuncSetAttribute(hgemm_persist_kernel<1, false>, cudaFuncAttributeMaxDynamicSharedMemorySize, PGEMM_SMEM);
    cudaFuncSetAttribute(hgemm_kernel<0>, cudaFuncAttributeMaxDynamicSharedMemorySize, GEMM_SMEM);

    // weight transpose + fp16 round, both layers batched via z
    wtconv_kernel<<<dim3(24, 8, 2), dim3(32, 8)>>>(qkvw, wth,          256, 768,
                                                   (size_t)Dd * 768, WLSTRIDE);
    wtconv_kernel<<<dim3(8,  8, 2), dim3(32, 8)>>>(ow,   wth + 196608, 256, 256,
                                                   (size_t)Dd * Dd,  WLSTRIDE);
    wtconv_kernel<<<dim3(32, 8, 2), dim3(32, 8)>>>(fw1,  wth + 262144, 256, 1024,
                                                   (size_t)Dd * FF,  WLSTRIDE);
    wtconv_kernel<<<dim3(8, 32, 2), dim3(32, 8)>>>(fw2,  wth + 524288, 1024, 256,
                                                   (size_t)FF * Dd,  WLSTRIDE);

    // xm = x + spe -> fp16 stream
    {
        int n4 = MROWS * Dd / 4;
        add_spe_kernel<<<(n4 + 255) / 256, 256>>>(x, spe, xmh, n4);
    }

    const int lnBlocks = MROWS / 8;
    for (int layer = 0; layer < 2; layer++) {
        int shifted = (layer == 1);
        size_t wo = (size_t)layer * WLSTRIDE;

        cpb_kernel<<<WIN2 * WIN2, 256>>>(cw1 + layer * 2 * CPBH, cb1 + layer * CPBH,
                                         cw2 + layer * CPBH * HEADS, cb2 + layer * HEADS, cpb);

        // qkv = (rolled) xm @ qkv_w -> fp16   (persistent, 6 x 24 = 144 CTAs)
        if (shifted)
            hgemm_persist_kernel<0, true><<<dim3(6, 24), 256, PGEMM_SMEM>>>(
                xmh, wth + wo, nullptr, qkv, 768, 24);
        else
            hgemm_persist_kernel<0, false><<<dim3(6, 24), 256, PGEMM_SMEM>>>(
                xmh, wth + wo, nullptr, qkv, 768, 24);

        attn_kernel<<<dim3(NW, HEADS, Bb), 256>>>(qkv, tau + layer * HEADS, cpb, ath, shifted);

        // o-proj -> tmp (fp16)   (persistent, 2 x 74 = 148 CTAs)
        hgemm_persist_kernel<0, false><<<dim3(2, 74), 256, PGEMM_SMEM>>>(
            ath, wth + wo + 196608, ob + layer * Dd, tmph, 256, 74);

        // xm += LN(oproj) (rolled back if shifted)
        ln_residual_kernel<<<lnBlocks, 256>>>(tmph, ln1g + layer * Dd, ln1b + layer * Dd,
                                              xmh, shifted);

        // ffn1: gelu(xm @ fw1 + fb1) -> fp16   (persistent, 8 x 18 = 144 CTAs)
        hgemm_persist_kernel<1, false><<<dim3(8, 18), 256, PGEMM_SMEM>>>(
            xmh, wth + wo + 262144, fb1 + layer * FF, ffh, 1024, 18);

        // ffn2 -> tmp (fp16)   (streaming, K=1024)
        hgemm_kernel<0><<<dim3(2, MROWS / 256), 256, GEMM_SMEM>>>(
            ffh, wth + wo + 524288, fb2 + layer * Dd, tmph, 256, 1024);

        // xm += LN(ffn2)
        ln_residual_kernel<<<lnBlocks, 256>>>(tmph, ln2g + layer * Dd, ln2b + layer * Dd,
                                              xmh, 0);
    }

    ln_final_kernel<<<MROWS / 8, 256>>>(xmh, ng, nb, out);
}

// round 15
// speedup vs baseline: 1.1210x; 1.0666x over previous
#include <cuda_runtime.h>
#include <cuda_fp16.h>
#include <cstdint>
#include <math.h>

#define Bb     16
#define Hh     56
#define Wd     56
#define Nn     3136
#define Dd     256
#define HEADS  8
#define HD     32
#define WIN    7
#define WIN2   49
#define NWH    8
#define NW     64
#define DISP   3
#define FF     1024
#define CPBH   512
#define EPSLN  1e-5f
#define MROWS  50176   // B * N
#define MTILES 196     // MROWS / 256

// ================= PTX helpers =================
__device__ __forceinline__ uint32_t smem_to_u32(const void* p) {
    uint32_t a;
    asm("{ .reg .u64 t; cvta.to.shared.u64 t, %1; cvt.u32.u64 %0, t; }" : "=r"(a) : "l"(p));
    return a;
}
#define CP_ASYNC_CG(dst, src) \
    asm volatile("cp.async.cg.shared.global [%0], [%1], 16;" :: "r"(dst), "l"(src))
#define CP_ASYNC_COMMIT() asm volatile("cp.async.commit_group;" ::: "memory")
#define CP_ASYNC_WAIT(n)  asm volatile("cp.async.wait_group %0;" :: "n"(n) : "memory")

__device__ __forceinline__ void ldsm_x4(uint32_t* r, uint32_t addr) {
    asm volatile("ldmatrix.sync.aligned.m8n8.x4.shared.b16 {%0,%1,%2,%3}, [%4];"
        : "=r"(r[0]), "=r"(r[1]), "=r"(r[2]), "=r"(r[3]) : "r"(addr));
}
__device__ __forceinline__ void mma_f16(float* c, const uint32_t* a, const uint32_t* b) {
    asm volatile("mma.sync.aligned.m16n8k16.row.col.f32.f16.f16.f32 "
        "{%0,%1,%2,%3},{%4,%5,%6,%7},{%8,%9},{%0,%1,%2,%3};"
        : "+f"(c[0]), "+f"(c[1]), "+f"(c[2]), "+f"(c[3])
        : "r"(a[0]), "r"(a[1]), "r"(a[2]), "r"(a[3]), "r"(b[0]), "r"(b[1]));
}

// ================= device scratch =================
__device__ __half g_xmh [MROWS * Dd];          // fp16 residual stream
__device__ __half g_qkv [MROWS * 3 * Dd];
__device__ __half g_ath [MROWS * Dd];
__device__ __half g_ffh [MROWS * FF];
__device__ __half g_tmp [MROWS * Dd];
__device__ float  g_cpb [HEADS * WIN2 * WIN2];
// transposed fp16 weights, per layer:
// [0) qkvT 768x256 | 196608) owT 256x256 | 262144) fw1T 1024x256 | 524288) fw2T 256x1024
#define WLSTRIDE 786432
__device__ __half g_wth [2 * WLSTRIDE];

// ================= small helpers =================
__device__ __forceinline__ uint32_t pack_h2(float a, float b) {
    __half2 h = __floats2half2_rn(a, b);
    return *(uint32_t*)&h;
}

// ================= add SPE (fp16 out) =================
__global__ void add_spe_kernel(const float* __restrict__ x, const float* __restrict__ spe,
                               __half* __restrict__ xh, int n4) {
    int i = blockIdx.x * blockDim.x + threadIdx.x;
    if (i < n4) {
        float4 a = ((const float4*)x)[i];
        float4 b = ((const float4*)spe)[i];
        uint2 h;
        h.x = pack_h2(a.x + b.x, a.y + b.y);
        h.y = pack_h2(a.z + b.z, a.w + b.w);
        ((uint2*)xh)[i] = h;
    }
}

// ================= weight transpose + fp16 round: W[K,N] -> T[N,K], z = layer =================
__global__ void wtconv_kernel(const float* __restrict__ W, __half* __restrict__ Th,
                              int K, int N, size_t wstride, size_t tstride) {
    W  += (size_t)blockIdx.z * wstride;
    Th += (size_t)blockIdx.z * tstride;
    __shared__ float t[32][33];
    int bn = blockIdx.x * 32, bk = blockIdx.y * 32;
    int tx = threadIdx.x, ty = threadIdx.y;
    #pragma unroll
    for (int j = 0; j < 32; j += 8)
        t[ty + j][tx] = W[(size_t)(bk + ty + j) * N + bn + tx];
    __syncthreads();
    #pragma unroll
    for (int j = 0; j < 32; j += 8) {
        Th[(size_t)(bn + ty + j) * K + bk + tx] = __float2half_rn(t[tx][ty + j]);
    }
}

// ================= CPB MLP =================
__global__ void cpb_kernel(const float* __restrict__ cw1, const float* __restrict__ cb1,
                           const float* __restrict__ cw2, const float* __restrict__ cb2,
                           float* __restrict__ cpb) {
    int p = blockIdx.x;
    int i = p / WIN2, j = p % WIN2;
    float dy = (float)(j / WIN - i / WIN);
    float dx = (float)(j % WIN - i % WIN);
    float r0 = ((dy > 0.f) - (dy < 0.f)) * log1pf(fabsf(dy));
    float r1 = ((dx > 0.f) - (dx < 0.f)) * log1pf(fabsf(dx));
    int tid = threadIdx.x;
    int c0 = tid, c1 = tid + 256;
    float h0 = fmaxf(r0 * cw1[c0] + r1 * cw1[CPBH + c0] + cb1[c0], 0.f);
    float h1 = fmaxf(r0 * cw1[c1] + r1 * cw1[CPBH + c1] + cb1[c1], 0.f);
    __shared__ float red[256];
    for (int h = 0; h < HEADS; h++) {
        red[tid] = h0 * cw2[c0 * HEADS + h] + h1 * cw2[c1 * HEADS + h];
        __syncthreads();
        for (int s = 128; s > 0; s >>= 1) {
            if (tid < s) red[tid] += red[tid + s];
            __syncthreads();
        }
        if (tid == 0) cpb[h * (WIN2 * WIN2) + p] = red[0] + cb2[h];
        __syncthreads();
    }
}

// ================= shared epilogue (fp16 out only) =================
template<int ACT>
__device__ __forceinline__ void gemm_epilogue(
    float acc[4][8][4], int bm, int bn, int warpM, int warpN, int lane,
    const float* __restrict__ bias, __half* __restrict__ Ch, int Ntot) {
    const int g = lane >> 2, q = lane & 3;
    #pragma unroll
    for (int m = 0; m < 4; m++) {
        #pragma unroll
        for (int n = 0; n < 8; n++) {
            int col = bn + warpN * 64 + n * 8 + 2 * q;
            float b0 = bias ? bias[col] : 0.f;
            float b1 = bias ? bias[col + 1] : 0.f;
            #pragma unroll
            for (int hrow = 0; hrow < 2; hrow++) {
                int row = bm + warpM * 64 + m * 16 + g + hrow * 8;
                float v0 = acc[m][n][hrow * 2 + 0] + b0;
                float v1 = acc[m][n][hrow * 2 + 1] + b1;
                if (ACT == 1) {
                    v0 = v0 * 0.5f * (1.f + erff(v0 * 0.7071067811865476f));
                    v1 = v1 * 0.5f * (1.f + erff(v1 * 0.7071067811865476f));
                }
                *(uint32_t*)(Ch + (size_t)row * Ntot + col) = pack_h2(v0, v1);
            }
        }
    }
}

// ================= persistent-B HMMA GEMM, K = 256 fixed, BK = 64 =================
#define SAS2     72                          // padded A row stride (halves), 144B
#define PA_STAGE (256 * SAS2 * 2)            // 36864
#define PSTAGES  3
#define PB_STRIDE 264
#define PB_BYTES (128 * PB_STRIDE * 2)       // 67584
#define PGEMM_SMEM (PB_BYTES + PSTAGES * PA_STAGE)  // 178176

template<int ACT, bool GATHER>
__global__ void __launch_bounds__(256, 1)
hgemm_persist_kernel(const __half* __restrict__ Ah, const __half* __restrict__ Bth,
                     const float* __restrict__ bias, __half* __restrict__ Ch,
                     int Ntot, int G) {
    extern __shared__ char smem_raw[];
    const uint32_t sB = smem_to_u32(smem_raw);
    const uint32_t sA = sB + PB_BYTES;
    const int tid  = threadIdx.x;
    const int lane = tid & 31, wid = tid >> 5;
    const int warpM = wid >> 1, warpN = wid & 1;
    const int bn = blockIdx.x * 128;
    const int g  = blockIdx.y;

    // ---- load B panel once (128 x 256 fp16) ----
    #pragma unroll
    for (int it = 0; it < 16; it++) {
        int idx = tid + it * 256;
        int n = idx >> 5, q = idx & 31;
        CP_ASYNC_CG(sB + (uint32_t)(n * (PB_STRIDE * 2) + q * 16),
                    Bth + (size_t)(bn + n) * 256 + q * 8);
    }
    CP_ASYNC_COMMIT();

    // per-thread A loader geometry: 256 rows x 8 chunks = 2048 -> 8/thread
    int arow_s[8], acol_s[8];
    uint32_t aoff[8];
    #pragma unroll
    for (int l = 0; l < 8; l++) {
        int c = tid + l * 256;
        int r = c >> 3, q = c & 7;
        arow_s[l] = r; acol_s[l] = q * 8;
        aoff[l] = (uint32_t)(r * (SAS2 * 2) + q * 16);
    }

    const int ntl = (MTILES - 1 - g) / G + 1;
    const int total_cc = ntl * 4;            // 4 x 64-K chunks per tile

    auto issue = [&](int cc, int stg_i) {
        int tile = cc >> 2, c = cc & 3;
        int bm = (g + tile * G) * 256;
        uint32_t stg = sA + (uint32_t)stg_i * PA_STAGE;
        int kt = c << 6;
        #pragma unroll
        for (int l = 0; l < 8; l++) {
            int gm = bm + arow_s[l];
            if (GATHER) {
                int b = gm / Nn, rem = gm - b * Nn;
                int h = rem / Wd, w = rem - h * Wd;
                h = (h + DISP) % Hh; w = (w + DISP) % Wd;
                gm = b * Nn + h * Wd + w;
            }
            CP_ASYNC_CG(stg + aoff[l], Ah + (size_t)gm * 256 + kt + acol_s[l]);
        }
    };

    float acc[4][8][4];
    #pragma unroll
    for (int m = 0; m < 4; m++)
        #pragma unroll
        for (int n = 0; n < 8; n++)
            #pragma unroll
            for (int e = 0; e < 4; e++) acc[m][n][e] = 0.f;

    const int arow  = (lane & 15);
    const int ahalf = (lane >> 4);
    const int bidx  = lane & 7;
    const int bkh   = (lane >> 3) & 1;
    const int bsub  = lane >> 4;

    issue(0, 0); CP_ASYNC_COMMIT();
    if (total_cc > 1) issue(1, 1);
    CP_ASYNC_COMMIT();

    int sc = 0, scn = 2;
    for (int cc = 0; cc < total_cc; cc++) {
        CP_ASYNC_WAIT(1);
        __syncthreads();
        if (cc + 2 < total_cc) issue(cc + 2, scn);
        CP_ASYNC_COMMIT();

        uint32_t stg = sA + (uint32_t)sc * PA_STAGE;
        const int c = cc & 3;
        #pragma unroll
        for (int ks = 0; ks < 4; ks++) {
            const int kg = c * 4 + ks;        // 16-K step in full K (0..15)
            uint32_t ah[4][4], bh[8][2];
            #pragma unroll
            for (int m = 0; m < 4; m++) {
                uint32_t off = (uint32_t)((warpM * 64 + m * 16 + arow) * (SAS2 * 2)
                                          + (ks * 16 + ahalf * 8) * 2);
                ldsm_x4(ah[m], stg + off);
            }
            #pragma unroll
            for (int pr = 0; pr < 4; pr++) {
                uint32_t off = (uint32_t)((warpN * 64 + pr * 16 + bsub * 8 + bidx) * (PB_STRIDE * 2)
                                          + (kg * 16 + bkh * 8) * 2);
                uint32_t t[4];
                ldsm_x4(t, sB + off);
                bh[pr * 2][0] = t[0]; bh[pr * 2][1] = t[1];
                bh[pr * 2 + 1][0] = t[2]; bh[pr * 2 + 1][1] = t[3];
            }
            #pragma unroll
            for (int m = 0; m < 4; m++)
                #pragma unroll
                for (int n = 0; n < 8; n++) mma_f16(acc[m][n], ah[m], bh[n]);
        }
        sc = (sc == 2) ? 0 : sc + 1;
        scn = (scn == 2) ? 0 : scn + 1;

        if (c == 3) {
            int bm = (g + (cc >> 2) * G) * 256;
            gemm_epilogue<ACT>(acc, bm, bn, warpM, warpN, lane, bias, Ch, Ntot);
            #pragma unroll
            for (int m = 0; m < 4; m++)
                #pragma unroll
                for (int n = 0; n < 8; n++)
                    #pragma unroll
                    for (int e = 0; e < 4; e++) acc[m][n][e] = 0.f;
        }
    }
}

// ================= streaming HMMA GEMM (K=1024 ffn2), BK = 64 =================
#define SB_OFF   (256 * SAS2 * 2)            // 36864 (A part)
#define STAGE_B2 (SB_OFF + 128 * SAS2 * 2)   // 55296
#define GEMM_SMEM (3 * STAGE_B2)             // 165888

template<int ACT>
__global__ void __launch_bounds__(256, 1)
hgemm_kernel(const __half* __restrict__ Ah, const __half* __restrict__ Bth,
             const float* __restrict__ bias, __half* __restrict__ Ch,
             int Ntot, int K) {
    extern __shared__ char smem_raw[];
    const uint32_t sbase = smem_to_u32(smem_raw);
    const int tid  = threadIdx.x;
    const int lane = tid & 31, wid = tid >> 5;
    const int warpM = wid >> 1, warpN = wid & 1;
    const int bm = blockIdx.y * 256, bn = blockIdx.x * 128;

    const __half *pAh[8], *pBh[4];
    uint32_t aoff[8], boff[4];
    #pragma unroll
    for (int l = 0; l < 8; l++) {
        int c = tid + l * 256;
        int r = c >> 3, q = c & 7;
        pAh[l] = Ah + (size_t)(bm + r) * K + q * 8;
        aoff[l] = (uint32_t)(r * (SAS2 * 2) + q * 16);
    }
    #pragma unroll
    for (int l = 0; l < 4; l++) {
        int c = tid + l * 256;
        int r = c >> 3, q = c & 7;
        pBh[l] = Bth + (size_t)(bn + r) * K + q * 8;
        boff[l] = (uint32_t)(r * (SAS2 * 2) + q * 16);
    }

    float acc[4][8][4];
    #pragma unroll
    for (int m = 0; m < 4; m++)
        #pragma unroll
        for (int n = 0; n < 8; n++)
            #pragma unroll
            for (int e = 0; e < 4; e++) acc[m][n][e] = 0.f;

    const int nch = K >> 6;                   // 64-K chunks

    auto load_stage = [&](int c, int stg_i) {
        uint32_t stg = sbase + (uint32_t)stg_i * STAGE_B2;
        int kt = c << 6;
        #pragma unroll
        for (int l = 0; l < 8; l++)
            CP_ASYNC_CG(stg + aoff[l], pAh[l] + kt);
        #pragma unroll
        for (int l = 0; l < 4; l++)
            CP_ASYNC_CG(stg + SB_OFF + boff[l], pBh[l] + kt);
    };

    const int arow  = (lane & 15);
    const int ahalf = (lane >> 4);
    const int bidx  = lane & 7;
    const int bkh   = (lane >> 3) & 1;
    const int bsub  = lane >> 4;

    load_stage(0, 0); CP_ASYNC_COMMIT();
    if (nch > 1) load_stage(1, 1);
    CP_ASYNC_COMMIT();

    int sc = 0, scn = 2;
    for (int c = 0; c < nch; c++) {
        CP_ASYNC_WAIT(1);
        __syncthreads();
        if (c + 2 < nch) load_stage(c + 2, scn);
        CP_ASYNC_COMMIT();

        uint32_t stg = sbase + (uint32_t)sc * STAGE_B2;
        #pragma unroll
        for (int ks = 0; ks < 4; ks++) {
            uint32_t ah[4][4], bh[8][2];
            #pragma unroll
            for (int m = 0; m < 4; m++) {
                uint32_t off = (uint32_t)((warpM * 64 + m * 16 + arow) * (SAS2 * 2)
                                          + (ks * 16 + ahalf * 8) * 2);
                ldsm_x4(ah[m], stg + off);
            }
            #pragma unroll
            for (int pr = 0; pr < 4; pr++) {
                uint32_t off = (uint32_t)((warpN * 64 + pr * 16 + bsub * 8 + bidx) * (SAS2 * 2)
                                          + (ks * 16 + bkh * 8) * 2);
                uint32_t t[4];
                ldsm_x4(t, stg + SB_OFF + off);
                bh[pr * 2][0] = t[0]; bh[pr * 2][1] = t[1];
                bh[pr * 2 + 1][0] = t[2]; bh[pr * 2 + 1][1] = t[3];
            }
            #pragma unroll
            for (int m = 0; m < 4; m++)
                #pragma unroll
                for (int n = 0; n < 8; n++) mma_f16(acc[m][n], ah[m], bh[n]);
        }
        sc = (sc == 2) ? 0 : sc + 1;
        scn = (scn == 2) ? 0 : scn + 1;
    }

    gemm_epilogue<ACT>(acc, bm, bn, warpM, warpN, lane, bias, Ch, Ntot);
}

// ================= window attention (fp32-smem, occ-boosted) =================
#define QS 34
#define DS 52
__global__ void __launch_bounds__(256, 6)
attn_kernel(const __half* __restrict__ qkv, const float* __restrict__ tau,
            const float* __restrict__ cpb, __half* __restrict__ outh, int shifted) {
    __shared__ float sq[64 * QS];
    __shared__ float sk[64 * QS];
    __shared__ float sv[49 * QS];
    __shared__ float sd[64 * DS];

    const int wi   = blockIdx.x;
    const int head = blockIdx.y;
    const int b    = blockIdx.z;
    const int wh = wi >> 3, ww = wi & 7;
    const int tid = threadIdx.x;

    for (int e = tid; e < WIN2 * 12; e += 256) {
        int t = e / (WIN2 * 4);
        int rem = e - t * (WIN2 * 4);
        int r = rem >> 2, c = rem & 3;
        int i = r / WIN, j = r % WIN;
        int m = b * Nn + (wh * WIN + i) * Wd + (ww * WIN + j);
        uint4 u = *(const uint4*)(qkv + (size_t)m * 768 + t * 256 + head * HD + c * 8);
        float* dst = (t == 0 ? sq : (t == 1 ? sk : sv)) + r * QS + c * 8;
        const __half2* hp = (const __half2*)&u;
        #pragma unroll
        for (int kk = 0; kk < 4; kk++) {
            float2 f = __half22float2(hp[kk]);
            *(float2*)(dst + kk * 2) = f;
        }
    }
    for (int e = tid; e < 15 * 32; e += 256) {
        int r = WIN2 + (e >> 5), d = e & 31;
        sq[r * QS + d] = 0.f;
        sk[r * QS + d] = 0.f;
    }
    __syncthreads();

    for (int t = tid; t < 2 * WIN2; t += 256) {
        float* row = (t < WIN2) ? (sq + t * QS) : (sk + (t - WIN2) * QS);
        float s = 0.f;
        #pragma unroll
        for (int d = 0; d < HD; d += 2) {
            float2 v = *(float2*)(row + d);
            s += v.x * v.x + v.y * v.y;
        }
        float inv = 1.f / fmaxf(sqrtf(s), 1e-12f);
        #pragma unroll
        for (int d = 0; d < HD; d += 2) {
            float2 v = *(float2*)(row + d);
            v.x *= inv; v.y *= inv;
            *(float2*)(row + d) = v;
        }
    }
    __syncthreads();

    const float tscale = 1.f / fmaxf(tau[head], 0.01f);
    const int tx = tid & 15, ty = tid >> 4;

    float acc[4][4];
    #pragma unroll
    for (int u = 0; u < 4; u++)
        #pragma unroll
        for (int v = 0; v < 4; v++) acc[u][v] = 0.f;
    #pragma unroll
    for (int kk = 0; kk < HD; kk += 2) {
        float2 a2[4], b2[4];
        #pragma unroll
        for (int u = 0; u < 4; u++) a2[u] = *(float2*)&sq[(ty + u * 16) * QS + kk];
        #pragma unroll
        for (int v = 0; v < 4; v++) b2[v] = *(float2*)&sk[(tx + v * 16) * QS + kk];
        #pragma unroll
        for (int u = 0; u < 4; u++)
            #pragma unroll
            for (int v = 0; v < 4; v++)
                acc[u][v] += a2[u].x * b2[v].x + a2[u].y * b2[v].y;
    }
    #pragma unroll
    for (int u = 0; u < 4; u++) {
        int i = ty + u * 16;
        if (i >= WIN2) continue;
        #pragma unroll
        for (int v = 0; v < 4; v++) {
            int j = tx + v * 16;
            if (j >= WIN2) continue;
            float val = acc[u][v] * tscale + cpb[head * (WIN2 * WIN2) + i * WIN2 + j];
            if (shifted) {
                if (wh == NWH - 1 && ((i >= 28) != (j >= 28))) val = -1e30f;
                if (ww == NWH - 1 && (((i % WIN) >= 4) != ((j % WIN) >= 4))) val = -1e30f;
            }
            sd[i * DS + j] = val;
        }
    }
    __syncthreads();

    const int lane = tid & 31, wrp = tid >> 5;
    for (int r = wrp; r < WIN2; r += 8) {
        float v0 = sd[r * DS + lane];
        float v1 = (lane + 32 < WIN2) ? sd[r * DS + lane + 32] : -3e38f;
        float mx = fmaxf(v0, v1);
        #pragma unroll
        for (int o = 16; o > 0; o >>= 1) mx = fmaxf(mx, __shfl_xor_sync(~0u, mx, o));
        float e0 = __expf(v0 - mx);
        float e1 = (lane + 32 < WIN2) ? __expf(v1 - mx) : 0.f;
        float s = e0 + e1;
        #pragma unroll
        for (int o = 16; o > 0; o >>= 1) s += __shfl_xor_sync(~0u, s, o);
        float inv = 1.f / s;
        sd[r * DS + lane] = e0 * inv;
        if (lane + 32 < WIN2) sd[r * DS + lane + 32] = e1 * inv;
    }
    __syncthreads();

    float o2[4][2];
    #pragma unroll
    for (int u = 0; u < 4; u++) { o2[u][0] = 0.f; o2[u][1] = 0.f; }
    for (int j = 0; j < 48; j += 2) {
        float2 p2[4];
        #pragma unroll
        for (int u = 0; u < 4; u++) p2[u] = *(float2*)&sd[(ty + u * 16) * DS + j];
        float2 va = *(float2*)&sv[j * QS + tx * 2];
        float2 vb = *(float2*)&sv[(j + 1) * QS + tx * 2];
        #pragma unroll
        for (int u = 0; u < 4; u++) {
            o2[u][0] += p2[u].x * va.x + p2[u].y * vb.x;
            o2[u][1] += p2[u].x * va.y + p2[u].y * vb.y;
        }
    }
    {
        float2 vc = *(float2*)&sv[48 * QS + tx * 2];
        #pragma unroll
        for (int u = 0; u < 4; u++) {
            float p = sd[(ty + u * 16) * DS + 48];
            o2[u][0] += p * vc.x;
            o2[u][1] += p * vc.y;
        }
    }
    #pragma unroll
    for (int u = 0; u < 4; u++) {
        int i = ty + u * 16;
        if (i < WIN2) {
            int ii = i / WIN, jj = i % WIN;
            int m = b * Nn + (wh * WIN + ii) * Wd + (ww * WIN + jj);
            size_t off = (size_t)m * Dd + head * HD + tx * 2;
            *(uint32_t*)(outh + off) = pack_h2(o2[u][0], o2[u][1]);
        }
    }
}

// ================= LN + residual (fp16 stream, fp32 math) =================
__global__ void ln_residual_kernel(const __half* __restrict__ A, const float* __restrict__ g,
                                   const float* __restrict__ be, __half* __restrict__ xh,
                                   int gather) {
    int row = blockIdx.x * 8 + (threadIdx.x >> 5);
    int lane = threadIdx.x & 31;
    int src = row;
    if (gather) {
        int b = row / Nn, rem = row % Nn;
        int h = rem / Wd, w = rem % Wd;
        src = b * Nn + ((h + Hh - DISP) % Hh) * Wd + ((w + Wd - DISP) % Wd);
    }
    uint4 av = ((const uint4*)(A + (size_t)src * Dd))[lane];
    const __half2* hp = (const __half2*)&av;
    float vals[8];
    #pragma unroll
    for (int k = 0; k < 4; k++) {
        float2 f = __half22float2(hp[k]);
        vals[2 * k] = f.x; vals[2 * k + 1] = f.y;
    }
    float s = 0.f, s2 = 0.f;
    #pragma unroll
    for (int k = 0; k < 8; k++) { s += vals[k]; s2 += vals[k] * vals[k]; }
    #pragma unroll
    for (int o = 16; o > 0; o >>= 1) {
        s  += __shfl_xor_sync(~0u, s, o);
        s2 += __shfl_xor_sync(~0u, s2, o);
    }
    float mean = s * (1.f / Dd);
    float var  = s2 * (1.f / Dd) - mean * mean;
    float inv  = rsqrtf(var + EPSLN);

    float4 g0 = ((const float4*)g)[lane * 2],  g1 = ((const float4*)g)[lane * 2 + 1];
    float4 b0 = ((const float4*)be)[lane * 2], b1 = ((const float4*)be)[lane * 2 + 1];

    uint4* xp = (uint4*)(xh + (size_t)row * Dd + lane * 8);
    uint4 xv = *xp;
    const __half2* xh2 = (const __half2*)&xv;
    float r[8];
    #pragma unroll
    for (int k = 0; k < 4; k++) {
        float2 f = __half22float2(xh2[k]);
        r[2 * k] = f.x; r[2 * k + 1] = f.y;
    }
    r[0] += (vals[0] - mean) * inv * g0.x + b0.x;
    r[1] += (vals[1] - mean) * inv * g0.y + b0.y;
    r[2] += (vals[2] - mean) * inv * g0.z + b0.z;
    r[3] += (vals[3] - mean) * inv * g0.w + b0.w;
    r[4] += (vals[4] - mean) * inv * g1.x + b1.x;
    r[5] += (vals[5] - mean) * inv * g1.y + b1.y;
    r[6] += (vals[6] - mean) * inv * g1.z + b1.z;
    r[7] += (vals[7] - mean) * inv * g1.w + b1.w;
    uint4 ov;
    ov.x = pack_h2(r[0], r[1]); ov.y = pack_h2(r[2], r[3]);
    ov.z = pack_h2(r[4], r[5]); ov.w = pack_h2(r[6], r[7]);
    *xp = ov;
}

// ================= final LN (reads fp16 stream) =================
__global__ void ln_final_kernel(const __half* __restrict__ A, const float* __restrict__ g,
                                const float* __restrict__ be, float* __restrict__ out) {
    int row = blockIdx.x * 8 + (threadIdx.x >> 5);
    int lane = threadIdx.x & 31;
    uint4 av = ((const uint4*)(A + (size_t)row * Dd))[lane];
    const __half2* hp = (const __half2*)&av;
    float vals[8];
    #pragma unroll
    for (int k = 0; k < 4; k++) {
        float2 f = __half22float2(hp[k]);
        vals[2 * k] = f.x; vals[2 * k + 1] = f.y;
    }
    float s = 0.f, s2 = 0.f;
    #pragma unroll
    for (int k = 0; k < 8; k++) { s += vals[k]; s2 += vals[k] * vals[k]; }
    #pragma unroll
    for (int o = 16; o > 0; o >>= 1) {
        s  += __shfl_xor_sync(~0u, s, o);
        s2 += __shfl_xor_sync(~0u, s2, o);
    }
    float mean = s * (1.f / Dd);
    float var  = s2 * (1.f / Dd) - mean * mean;
    float inv  = rsqrtf(var + EPSLN);
    float4 g0 = ((const float4*)g)[lane * 2],  g1 = ((const float4*)g)[lane * 2 + 1];
    float4 b0 = ((const float4*)be)[lane * 2], b1 = ((const float4*)be)[lane * 2 + 1];
    float4 o0, o1;
    o0.x = (vals[0] - mean) * inv * g0.x + b0.x;
    o0.y = (vals[1] - mean) * inv * g0.y + b0.y;
    o0.z = (vals[2] - mean) * inv * g0.z + b0.z;
    o0.w = (vals[3] - mean) * inv * g0.w + b0.w;
    o1.x = (vals[4] - mean) * inv * g1.x + b1.x;
    o1.y = (vals[5] - mean) * inv * g1.y + b1.y;
    o1.z = (vals[6] - mean) * inv * g1.z + b1.z;
    o1.w = (vals[7] - mean) * inv * g1.w + b1.w;
    float4* out4 = (float4*)(out + (size_t)row * Dd + lane * 8);
    out4[0] = o0; out4[1] = o1;
}

// ================= launch =================
extern "C" void kernel_launch(void* const* d_in, const int* in_sizes, int n_in,
                              void* d_out, int out_size) {
    const float* x    = (const float*)d_in[0];
    const float* spe  = (const float*)d_in[1];
    const float* qkvw = (const float*)d_in[2];
    const float* tau  = (const float*)d_in[3];
    const float* cw1  = (const float*)d_in[4];
    const float* cb1  = (const float*)d_in[5];
    const float* cw2  = (const float*)d_in[6];
    const float* cb2  = (const float*)d_in[7];
    const float* ow   = (const float*)d_in[8];
    const float* ob   = (const float*)d_in[9];
    const float* ln1g = (const float*)d_in[10];
    const float* ln1b = (const float*)d_in[11];
    const float* fw1  = (const float*)d_in[12];
    const float* fb1  = (const float*)d_in[13];
    const float* fw2  = (const float*)d_in[14];
    const float* fb2  = (const float*)d_in[15];
    const float* ln2g = (const float*)d_in[16];
    const float* ln2b = (const float*)d_in[17];
    const float* ng   = (const float*)d_in[18];
    const float* nb   = (const float*)d_in[19];
    float* out = (float*)d_out;

    float *cpb;
    __half *xmh, *qkv, *ath, *ffh, *tmph, *wth;
    cudaGetSymbolAddress((void**)&cpb,  g_cpb);
    cudaGetSymbolAddress((void**)&xmh,  g_xmh);
    cudaGetSymbolAddress((void**)&qkv,  g_qkv);
    cudaGetSymbolAddress((void**)&ath,  g_ath);
    cudaGetSymbolAddress((void**)&ffh,  g_ffh);
    cudaGetSymbolAddress((void**)&tmph, g_tmp);
    cudaGetSymbolAddress((void**)&wth,  g_wth);

    cudaFuncSetAttribute(hgemm_persist_kernel<0, false>, cudaFuncAttributeMaxDynamicSharedMemorySize, PGEMM_SMEM);
    cudaFuncSetAttribute(hgemm_persist_kernel<0, true>,  cudaFuncAttributeMaxDynamicSharedMemorySize, PGEMM_SMEM);
    cudaFuncSetAttribute(hgemm_persist_kernel<1, false>, cudaFuncAttributeMaxDynamicSharedMemorySize, PGEMM_SMEM);
    cudaFuncSetAttribute(hgemm_kernel<0>, cudaFuncAttributeMaxDynamicSharedMemorySize, GEMM_SMEM);

    // weight transpose + fp16 round, both layers batched via z
    wtconv_kernel<<<dim3(24, 8, 2), dim3(32, 8)>>>(qkvw, wth,          256, 768,
                                                   (size_t)Dd * 768, WLSTRIDE);
    wtconv_kernel<<<dim3(8,  8, 2), dim3(32, 8)>>>(ow,   wth + 196608, 256, 256,
                                                   (size_t)Dd * Dd,  WLSTRIDE);
    wtconv_kernel<<<dim3(32, 8, 2), dim3(32, 8)>>>(fw1,  wth + 262144, 256, 1024,
                                                   (size_t)Dd * FF,  WLSTRIDE);
    wtconv_kernel<<<dim3(8, 32, 2), dim3(32, 8)>>>(fw2,  wth + 524288, 1024, 256,
                                                   (size_t)FF * Dd,  WLSTRIDE);

    // xm = x + spe -> fp16 stream
    {
        int n4 = MROWS * Dd / 4;
        add_spe_kernel<<<(n4 + 255) / 256, 256>>>(x, spe, xmh, n4);
    }

    const int lnBlocks = MROWS / 8;
    for (int layer = 0; layer < 2; layer++) {
        int shifted = (layer == 1);
        size_t wo = (size_t)layer * WLSTRIDE;

        cpb_kernel<<<WIN2 * WIN2, 256>>>(cw1 + layer * 2 * CPBH, cb1 + layer * CPBH,
                                         cw2 + layer * CPBH * HEADS, cb2 + layer * HEADS, cpb);

        // qkv = (rolled) xm @ qkv_w -> fp16   (persistent, 6 x 24 = 144 CTAs)
        if (shifted)
            hgemm_persist_kernel<0, true><<<dim3(6, 24), 256, PGEMM_SMEM>>>(
                xmh, wth + wo, nullptr, qkv, 768, 24);
        else
            hgemm_persist_kernel<0, false><<<dim3(6, 24), 256, PGEMM_SMEM>>>(
                xmh, wth + wo, nullptr, qkv, 768, 24);

        attn_kernel<<<dim3(NW, HEADS, Bb), 256>>>(qkv, tau + layer * HEADS, cpb, ath, shifted);

        // o-proj -> tmp (fp16)   (persistent, 2 x 74 = 148 CTAs)
        hgemm_persist_kernel<0, false><<<dim3(2, 74), 256, PGEMM_SMEM>>>(
            ath, wth + wo + 196608, ob + layer * Dd, tmph, 256, 74);

        // xm += LN(oproj) (rolled back if shifted)
        ln_residual_kernel<<<lnBlocks, 256>>>(tmph, ln1g + layer * Dd, ln1b + layer * Dd,
                                              xmh, shifted);

        // ffn1: gelu(xm @ fw1 + fb1) -> fp16   (persistent, 8 x 18 = 144 CTAs)
        hgemm_persist_kernel<1, false><<<dim3(8, 18), 256, PGEMM_SMEM>>>(
            xmh, wth + wo + 262144, fb1 + layer * FF, ffh, 1024, 18);

        // ffn2 -> tmp (fp16)   (streaming, K=1024, BK=64)
        hgemm_kernel<0><<<dim3(2, MROWS / 256), 256, GEMM_SMEM>>>(
            ffh, wth + wo + 524288, fb2 + layer * Dd, tmph, 256, 1024);

        // xm += LN(ffn2)
        ln_residual_kernel<<<lnBlocks, 256>>>(tmph, ln2g + layer * Dd, ln2b + layer * Dd,
                                              xmh, 0);
    }

    ln_final_kernel<<<MROWS / 8, 256>>>(xmh, ng, nb, out);
}

// round 16
// speedup vs baseline: 1.1996x; 1.0701x over previous
#include <cuda_runtime.h>
#include <cuda_fp16.h>
#include <cstdint>
#include <math.h>

#define Bb     16
#define Hh     56
#define Wd     56
#define Nn     3136
#define Dd     256
#define HEADS  8
#define HD     32
#define WIN    7
#define WIN2   49
#define NWH    8
#define NW     64
#define DISP   3
#define FF     1024
#define CPBH   512
#define EPSLN  1e-5f
#define MROWS  50176   // B * N
#define MTILES 196     // MROWS / 256

// ================= PTX helpers =================
__device__ __forceinline__ uint32_t smem_to_u32(const void* p) {
    uint32_t a;
    asm("{ .reg .u64 t; cvta.to.shared.u64 t, %1; cvt.u32.u64 %0, t; }" : "=r"(a) : "l"(p));
    return a;
}
#define CP_ASYNC_CG(dst, src) \
    asm volatile("cp.async.cg.shared.global [%0], [%1], 16;" :: "r"(dst), "l"(src))
#define CP_ASYNC_COMMIT() asm volatile("cp.async.commit_group;" ::: "memory")
#define CP_ASYNC_WAIT(n)  asm volatile("cp.async.wait_group %0;" :: "n"(n) : "memory")

__device__ __forceinline__ void ldsm_x4(uint32_t* r, uint32_t addr) {
    asm volatile("ldmatrix.sync.aligned.m8n8.x4.shared.b16 {%0,%1,%2,%3}, [%4];"
        : "=r"(r[0]), "=r"(r[1]), "=r"(r[2]), "=r"(r[3]) : "r"(addr));
}
__device__ __forceinline__ void mma_f16(float* c, const uint32_t* a, const uint32_t* b) {
    asm volatile("mma.sync.aligned.m16n8k16.row.col.f32.f16.f16.f32 "
        "{%0,%1,%2,%3},{%4,%5,%6,%7},{%8,%9},{%0,%1,%2,%3};"
        : "+f"(c[0]), "+f"(c[1]), "+f"(c[2]), "+f"(c[3])
        : "r"(a[0]), "r"(a[1]), "r"(a[2]), "r"(a[3]), "r"(b[0]), "r"(b[1]));
}

// ================= device scratch =================
__device__ __half g_xmh [MROWS * Dd];          // fp16 residual stream
__device__ __half g_qkv [MROWS * 3 * Dd];
__device__ __half g_ath [MROWS * Dd];
__device__ __half g_ffh [MROWS * FF];
__device__ __half g_tmp [MROWS * Dd];
__device__ float  g_cpb [HEADS * WIN2 * WIN2];
// transposed fp16 weights, per layer:
// [0) qkvT 768x256 | 196608) owT 256x256 | 262144) fw1T 1024x256 | 524288) fw2T 256x1024
#define WLSTRIDE 786432
__device__ __half g_wth [2 * WLSTRIDE];

// ================= small helpers =================
__device__ __forceinline__ uint32_t pack_h2(float a, float b) {
    __half2 h = __floats2half2_rn(a, b);
    return *(uint32_t*)&h;
}

// ================= add SPE (fp16 out) =================
__global__ void add_spe_kernel(const float* __restrict__ x, const float* __restrict__ spe,
                               __half* __restrict__ xh, int n4) {
    int i = blockIdx.x * blockDim.x + threadIdx.x;
    if (i < n4) {
        float4 a = ((const float4*)x)[i];
        float4 b = ((const float4*)spe)[i];
        uint2 h;
        h.x = pack_h2(a.x + b.x, a.y + b.y);
        h.y = pack_h2(a.z + b.z, a.w + b.w);
        ((uint2*)xh)[i] = h;
    }
}

// ================= weight transpose + fp16 round: W[K,N] -> T[N,K], z = layer =================
__global__ void wtconv_kernel(const float* __restrict__ W, __half* __restrict__ Th,
                              int K, int N, size_t wstride, size_t tstride) {
    W  += (size_t)blockIdx.z * wstride;
    Th += (size_t)blockIdx.z * tstride;
    __shared__ float t[32][33];
    int bn = blockIdx.x * 32, bk = blockIdx.y * 32;
    int tx = threadIdx.x, ty = threadIdx.y;
    #pragma unroll
    for (int j = 0; j < 32; j += 8)
        t[ty + j][tx] = W[(size_t)(bk + ty + j) * N + bn + tx];
    __syncthreads();
    #pragma unroll
    for (int j = 0; j < 32; j += 8) {
        Th[(size_t)(bn + ty + j) * K + bk + tx] = __float2half_rn(t[tx][ty + j]);
    }
}

// ================= CPB MLP =================
__global__ void cpb_kernel(const float* __restrict__ cw1, const float* __restrict__ cb1,
                           const float* __restrict__ cw2, const float* __restrict__ cb2,
                           float* __restrict__ cpb) {
    int p = blockIdx.x;
    int i = p / WIN2, j = p % WIN2;
    float dy = (float)(j / WIN - i / WIN);
    float dx = (float)(j % WIN - i % WIN);
    float r0 = ((dy > 0.f) - (dy < 0.f)) * log1pf(fabsf(dy));
    float r1 = ((dx > 0.f) - (dx < 0.f)) * log1pf(fabsf(dx));
    int tid = threadIdx.x;
    int c0 = tid, c1 = tid + 256;
    float h0 = fmaxf(r0 * cw1[c0] + r1 * cw1[CPBH + c0] + cb1[c0], 0.f);
    float h1 = fmaxf(r0 * cw1[c1] + r1 * cw1[CPBH + c1] + cb1[c1], 0.f);
    __shared__ float red[256];
    for (int h = 0; h < HEADS; h++) {
        red[tid] = h0 * cw2[c0 * HEADS + h] + h1 * cw2[c1 * HEADS + h];
        __syncthreads();
        for (int s = 128; s > 0; s >>= 1) {
            if (tid < s) red[tid] += red[tid + s];
            __syncthreads();
        }
        if (tid == 0) cpb[h * (WIN2 * WIN2) + p] = red[0] + cb2[h];
        __syncthreads();
    }
}

// ================= shared epilogue (fp16 out only) =================
template<int ACT>
__device__ __forceinline__ void gemm_epilogue(
    float acc[4][8][4], int bm, int bn, int warpM, int warpN, int lane,
    const float* __restrict__ bias, __half* __restrict__ Ch, int Ntot) {
    const int g = lane >> 2, q = lane & 3;
    #pragma unroll
    for (int m = 0; m < 4; m++) {
        #pragma unroll
        for (int n = 0; n < 8; n++) {
            int col = bn + warpN * 64 + n * 8 + 2 * q;
            float b0 = bias ? bias[col] : 0.f;
            float b1 = bias ? bias[col + 1] : 0.f;
            #pragma unroll
            for (int hrow = 0; hrow < 2; hrow++) {
                int row = bm + warpM * 64 + m * 16 + g + hrow * 8;
                float v0 = acc[m][n][hrow * 2 + 0] + b0;
                float v1 = acc[m][n][hrow * 2 + 1] + b1;
                if (ACT == 1) {
                    v0 = v0 * 0.5f * (1.f + erff(v0 * 0.7071067811865476f));
                    v1 = v1 * 0.5f * (1.f + erff(v1 * 0.7071067811865476f));
                }
                *(uint32_t*)(Ch + (size_t)row * Ntot + col) = pack_h2(v0, v1);
            }
        }
    }
}

// ================= persistent-B HMMA GEMM, K = 256 fixed, BK = 64 =================
#define SAS2     72                          // padded A row stride (halves), 144B
#define PA_STAGE (256 * SAS2 * 2)            // 36864
#define PSTAGES  3
#define PB_STRIDE 264
#define PB_BYTES (128 * PB_STRIDE * 2)       // 67584
#define PGEMM_SMEM (PB_BYTES + PSTAGES * PA_STAGE)  // 178176

template<int ACT, bool GATHER>
__global__ void __launch_bounds__(256, 1)
hgemm_persist_kernel(const __half* __restrict__ Ah, const __half* __restrict__ Bth,
                     const float* __restrict__ bias, __half* __restrict__ Ch,
                     int Ntot, int G) {
    extern __shared__ char smem_raw[];
    const uint32_t sB = smem_to_u32(smem_raw);
    const uint32_t sA = sB + PB_BYTES;
    const int tid  = threadIdx.x;
    const int lane = tid & 31, wid = tid >> 5;
    const int warpM = wid >> 1, warpN = wid & 1;
    const int bn = blockIdx.x * 128;
    const int g  = blockIdx.y;

    #pragma unroll
    for (int it = 0; it < 16; it++) {
        int idx = tid + it * 256;
        int n = idx >> 5, q = idx & 31;
        CP_ASYNC_CG(sB + (uint32_t)(n * (PB_STRIDE * 2) + q * 16),
                    Bth + (size_t)(bn + n) * 256 + q * 8);
    }
    CP_ASYNC_COMMIT();

    int arow_s[8], acol_s[8];
    uint32_t aoff[8];
    #pragma unroll
    for (int l = 0; l < 8; l++) {
        int c = tid + l * 256;
        int r = c >> 3, q = c & 7;
        arow_s[l] = r; acol_s[l] = q * 8;
        aoff[l] = (uint32_t)(r * (SAS2 * 2) + q * 16);
    }

    const int ntl = (MTILES - 1 - g) / G + 1;
    const int total_cc = ntl * 4;

    auto issue = [&](int cc, int stg_i) {
        int tile = cc >> 2, c = cc & 3;
        int bm = (g + tile * G) * 256;
        uint32_t stg = sA + (uint32_t)stg_i * PA_STAGE;
        int kt = c << 6;
        #pragma unroll
        for (int l = 0; l < 8; l++) {
            int gm = bm + arow_s[l];
            if (GATHER) {
                int b = gm / Nn, rem = gm - b * Nn;
                int h = rem / Wd, w = rem - h * Wd;
                h = (h + DISP) % Hh; w = (w + DISP) % Wd;
                gm = b * Nn + h * Wd + w;
            }
            CP_ASYNC_CG(stg + aoff[l], Ah + (size_t)gm * 256 + kt + acol_s[l]);
        }
    };

    float acc[4][8][4];
    #pragma unroll
    for (int m = 0; m < 4; m++)
        #pragma unroll
        for (int n = 0; n < 8; n++)
            #pragma unroll
            for (int e = 0; e < 4; e++) acc[m][n][e] = 0.f;

    const int arow  = (lane & 15);
    const int ahalf = (lane >> 4);
    const int bidx  = lane & 7;
    const int bkh   = (lane >> 3) & 1;
    const int bsub  = lane >> 4;

    issue(0, 0); CP_ASYNC_COMMIT();
    if (total_cc > 1) issue(1, 1);
    CP_ASYNC_COMMIT();

    int sc = 0, scn = 2;
    for (int cc = 0; cc < total_cc; cc++) {
        CP_ASYNC_WAIT(1);
        __syncthreads();
        if (cc + 2 < total_cc) issue(cc + 2, scn);
        CP_ASYNC_COMMIT();

        uint32_t stg = sA + (uint32_t)sc * PA_STAGE;
        const int c = cc & 3;
        #pragma unroll
        for (int ks = 0; ks < 4; ks++) {
            const int kg = c * 4 + ks;
            uint32_t ah[4][4], bh[8][2];
            #pragma unroll
            for (int m = 0; m < 4; m++) {
                uint32_t off = (uint32_t)((warpM * 64 + m * 16 + arow) * (SAS2 * 2)
                                          + (ks * 16 + ahalf * 8) * 2);
                ldsm_x4(ah[m], stg + off);
            }
            #pragma unroll
            for (int pr = 0; pr < 4; pr++) {
                uint32_t off = (uint32_t)((warpN * 64 + pr * 16 + bsub * 8 + bidx) * (PB_STRIDE * 2)
                                          + (kg * 16 + bkh * 8) * 2);
                uint32_t t[4];
                ldsm_x4(t, sB + off);
                bh[pr * 2][0] = t[0]; bh[pr * 2][1] = t[1];
                bh[pr * 2 + 1][0] = t[2]; bh[pr * 2 + 1][1] = t[3];
            }
            #pragma unroll
            for (int m = 0; m < 4; m++)
                #pragma unroll
                for (int n = 0; n < 8; n++) mma_f16(acc[m][n], ah[m], bh[n]);
        }
        sc = (sc == 2) ? 0 : sc + 1;
        scn = (scn == 2) ? 0 : scn + 1;

        if (c == 3) {
            int bm = (g + (cc >> 2) * G) * 256;
            gemm_epilogue<ACT>(acc, bm, bn, warpM, warpN, lane, bias, Ch, Ntot);
            #pragma unroll
            for (int m = 0; m < 4; m++)
                #pragma unroll
                for (int n = 0; n < 8; n++)
                    #pragma unroll
                    for (int e = 0; e < 4; e++) acc[m][n][e] = 0.f;
        }
    }
}

// ================= streaming HMMA GEMM (K=1024 ffn2), BK = 64 =================
#define SB_OFF   (256 * SAS2 * 2)            // 36864 (A part)
#define STAGE_B2 (SB_OFF + 128 * SAS2 * 2)   // 55296
#define GEMM_SMEM (3 * STAGE_B2)             // 165888

template<int ACT>
__global__ void __launch_bounds__(256, 1)
hgemm_kernel(const __half* __restrict__ Ah, const __half* __restrict__ Bth,
             const float* __restrict__ bias, __half* __restrict__ Ch,
             int Ntot, int K) {
    extern __shared__ char smem_raw[];
    const uint32_t sbase = smem_to_u32(smem_raw);
    const int tid  = threadIdx.x;
    const int lane = tid & 31, wid = tid >> 5;
    const int warpM = wid >> 1, warpN = wid & 1;
    const int bm = blockIdx.y * 256, bn = blockIdx.x * 128;

    const __half *pAh[8], *pBh[4];
    uint32_t aoff[8], boff[4];
    #pragma unroll
    for (int l = 0; l < 8; l++) {
        int c = tid + l * 256;
        int r = c >> 3, q = c & 7;
        pAh[l] = Ah + (size_t)(bm + r) * K + q * 8;
        aoff[l] = (uint32_t)(r * (SAS2 * 2) + q * 16);
    }
    #pragma unroll
    for (int l = 0; l < 4; l++) {
        int c = tid + l * 256;
        int r = c >> 3, q = c & 7;
        pBh[l] = Bth + (size_t)(bn + r) * K + q * 8;
        boff[l] = (uint32_t)(r * (SAS2 * 2) + q * 16);
    }

    float acc[4][8][4];
    #pragma unroll
    for (int m = 0; m < 4; m++)
        #pragma unroll
        for (int n = 0; n < 8; n++)
            #pragma unroll
            for (int e = 0; e < 4; e++) acc[m][n][e] = 0.f;

    const int nch = K >> 6;

    auto load_stage = [&](int c, int stg_i) {
        uint32_t stg = sbase + (uint32_t)stg_i * STAGE_B2;
        int kt = c << 6;
        #pragma unroll
        for (int l = 0; l < 8; l++)
            CP_ASYNC_CG(stg + aoff[l], pAh[l] + kt);
        #pragma unroll
        for (int l = 0; l < 4; l++)
            CP_ASYNC_CG(stg + SB_OFF + boff[l], pBh[l] + kt);
    };

    const int arow  = (lane & 15);
    const int ahalf = (lane >> 4);
    const int bidx  = lane & 7;
    const int bkh   = (lane >> 3) & 1;
    const int bsub  = lane >> 4;

    load_stage(0, 0); CP_ASYNC_COMMIT();
    if (nch > 1) load_stage(1, 1);
    CP_ASYNC_COMMIT();

    int sc = 0, scn = 2;
    for (int c = 0; c < nch; c++) {
        CP_ASYNC_WAIT(1);
        __syncthreads();
        if (c + 2 < nch) load_stage(c + 2, scn);
        CP_ASYNC_COMMIT();

        uint32_t stg = sbase + (uint32_t)sc * STAGE_B2;
        #pragma unroll
        for (int ks = 0; ks < 4; ks++) {
            uint32_t ah[4][4], bh[8][2];
            #pragma unroll
            for (int m = 0; m < 4; m++) {
                uint32_t off = (uint32_t)((warpM * 64 + m * 16 + arow) * (SAS2 * 2)
                                          + (ks * 16 + ahalf * 8) * 2);
                ldsm_x4(ah[m], stg + off);
            }
            #pragma unroll
            for (int pr = 0; pr < 4; pr++) {
                uint32_t off = (uint32_t)((warpN * 64 + pr * 16 + bsub * 8 + bidx) * (SAS2 * 2)
                                          + (ks * 16 + bkh * 8) * 2);
                uint32_t t[4];
                ldsm_x4(t, stg + SB_OFF + off);
                bh[pr * 2][0] = t[0]; bh[pr * 2][1] = t[1];
                bh[pr * 2 + 1][0] = t[2]; bh[pr * 2 + 1][1] = t[3];
            }
            #pragma unroll
            for (int m = 0; m < 4; m++)
                #pragma unroll
                for (int n = 0; n < 8; n++) mma_f16(acc[m][n], ah[m], bh[n]);
        }
        sc = (sc == 2) ? 0 : sc + 1;
        scn = (scn == 2) ? 0 : scn + 1;
    }

    gemm_epilogue<ACT>(acc, bm, bn, warpM, warpN, lane, bias, Ch, Ntot);
}

// ================= window attention: HMMA QK^T, FFMA AV =================
#define QSH 40            // fp16 q/k row stride (halves), 80B
#define QS  34            // fp32 v row stride
#define DS  52
__global__ void __launch_bounds__(256, 6)
attn_kernel(const __half* __restrict__ qkv, const float* __restrict__ tau,
            const float* __restrict__ cpb, __half* __restrict__ outh, int shifted) {
    __shared__ __half sqh[64 * QSH];
    __shared__ __half skh[64 * QSH];
    __shared__ float  sv [49 * QS];
    __shared__ float  sd [64 * DS];

    const int wi   = blockIdx.x;
    const int head = blockIdx.y;
    const int b    = blockIdx.z;
    const int wh = wi >> 3, ww = wi & 7;
    const int tid = threadIdx.x;

    // load: q,k verbatim fp16; v converted to fp32
    for (int e = tid; e < WIN2 * 12; e += 256) {
        int t = e / (WIN2 * 4);
        int rem = e - t * (WIN2 * 4);
        int r = rem >> 2, c = rem & 3;
        int i = r / WIN, j = r % WIN;
        int m = b * Nn + (wh * WIN + i) * Wd + (ww * WIN + j);
        uint4 u = *(const uint4*)(qkv + (size_t)m * 768 + t * 256 + head * HD + c * 8);
        if (t < 2) {
            __half* dst = (t == 0 ? sqh : skh) + r * QSH + c * 8;
            *(uint2*)(dst)     = make_uint2(u.x, u.y);
            *(uint2*)(dst + 4) = make_uint2(u.z, u.w);
        } else {
            float* dst = sv + r * QS + c * 8;
            const __half2* hp = (const __half2*)&u;
            #pragma unroll
            for (int kk = 0; kk < 4; kk++) {
                float2 f = __half22float2(hp[kk]);
                *(float2*)(dst + kk * 2) = f;
            }
        }
    }
    // zero-pad rows 49..63 of q,k (240 uint2 stores total)
    for (int e = tid; e < 240; e += 256) {
        int t = (e >= 120);
        int e2 = e - t * 120;
        int r = WIN2 + (e2 >> 3), d = (e2 & 7) * 4;
        *(uint2*)((t ? skh : sqh) + r * QSH + d) = make_uint2(0u, 0u);
    }
    __syncthreads();

    // l2-normalize rows of q,k (fp32 math, fp16 store)
    for (int t = tid; t < 2 * WIN2; t += 256) {
        __half* row = (t < WIN2) ? (sqh + t * QSH) : (skh + (t - WIN2) * QSH);
        float s = 0.f;
        #pragma unroll
        for (int d = 0; d < HD; d += 2) {
            float2 v = __half22float2(*(__half2*)(row + d));
            s += v.x * v.x + v.y * v.y;
        }
        float inv = 1.f / fmaxf(sqrtf(s), 1e-12f);
        #pragma unroll
        for (int d = 0; d < HD; d += 2) {
            float2 v = __half22float2(*(__half2*)(row + d));
            *(uint32_t*)(row + d) = pack_h2(v.x * inv, v.y * inv);
        }
    }
    __syncthreads();

    const float tscale = 1.f / fmaxf(tau[head], 0.01f);
    const int lane = tid & 31, wid = tid >> 5;

    // ---- QK^T via HMMA: warp = (mrow 0..3) x (nhalf 0..1), 16x32 output each ----
    {
        const int mrow  = wid & 3, nhalf = wid >> 2;
        const int arow  = lane & 15, ahalf = lane >> 4;
        const int bidx  = lane & 7, bkh = (lane >> 3) & 1, bsub = lane >> 4;
        const uint32_t sq_u = smem_to_u32(sqh);
        const uint32_t sk_u = smem_to_u32(skh);

        float dacc[4][4];
        #pragma unroll
        for (int nt = 0; nt < 4; nt++)
            #pragma unroll
            for (int e = 0; e < 4; e++) dacc[nt][e] = 0.f;

        #pragma unroll
        for (int ks = 0; ks < 2; ks++) {
            uint32_t a[4], bh[4][2];
            ldsm_x4(a, sq_u + (uint32_t)(((mrow * 16 + arow) * QSH
                                          + ks * 16 + ahalf * 8) * 2));
            #pragma unroll
            for (int pr = 0; pr < 2; pr++) {
                uint32_t t4[4];
                ldsm_x4(t4, sk_u + (uint32_t)(((nhalf * 32 + pr * 16 + bsub * 8 + bidx) * QSH
                                               + ks * 16 + bkh * 8) * 2));
                bh[pr * 2][0] = t4[0]; bh[pr * 2][1] = t4[1];
                bh[pr * 2 + 1][0] = t4[2]; bh[pr * 2 + 1][1] = t4[3];
            }
            #pragma unroll
            for (int nt = 0; nt < 4; nt++) mma_f16(dacc[nt], a, bh[nt]);
        }

        // scatter fragments -> sd with scale + cpb + shift masks
        const int g = lane >> 2, q = lane & 3;
        #pragma unroll
        for (int hrow = 0; hrow < 2; hrow++) {
            int i = mrow * 16 + g + hrow * 8;
            if (i < WIN2) {
                #pragma unroll
                for (int nt = 0; nt < 4; nt++) {
                    #pragma unroll
                    for (int e = 0; e < 2; e++) {
                        int j = nhalf * 32 + nt * 8 + 2 * q + e;
                        if (j >= WIN2) continue;
                        float val = dacc[nt][hrow * 2 + e] * tscale
                                  + cpb[head * (WIN2 * WIN2) + i * WIN2 + j];
                        if (shifted) {
                            if (wh == NWH - 1 && ((i >= 28) != (j >= 28))) val = -1e30f;
                            if (ww == NWH - 1 && (((i % WIN) >= 4) != ((j % WIN) >= 4))) val = -1e30f;
                        }
                        sd[i * DS + j] = val;
                    }
                }
            }
        }
    }
    __syncthreads();

    // softmax (one warp per row)
    const int wrp = wid;
    for (int r = wrp; r < WIN2; r += 8) {
        float v0 = sd[r * DS + lane];
        float v1 = (lane + 32 < WIN2) ? sd[r * DS + lane + 32] : -3e38f;
        float mx = fmaxf(v0, v1);
        #pragma unroll
        for (int o = 16; o > 0; o >>= 1) mx = fmaxf(mx, __shfl_xor_sync(~0u, mx, o));
        float e0 = __expf(v0 - mx);
        float e1 = (lane + 32 < WIN2) ? __expf(v1 - mx) : 0.f;
        float s = e0 + e1;
        #pragma unroll
        for (int o = 16; o > 0; o >>= 1) s += __shfl_xor_sync(~0u, s, o);
        float inv = 1.f / s;
        sd[r * DS + lane] = e0 * inv;
        if (lane + 32 < WIN2) sd[r * DS + lane + 32] = e1 * inv;
    }
    __syncthreads();

    // AV (FFMA, fp32)
    const int tx = tid & 15, ty = tid >> 4;
    float o2[4][2];
    #pragma unroll
    for (int u = 0; u < 4; u++) { o2[u][0] = 0.f; o2[u][1] = 0.f; }
    for (int j = 0; j < 48; j += 2) {
        float2 p2[4];
        #pragma unroll
        for (int u = 0; u < 4; u++) p2[u] = *(float2*)&sd[(ty + u * 16) * DS + j];
        float2 va = *(float2*)&sv[j * QS + tx * 2];
        float2 vb = *(float2*)&sv[(j + 1) * QS + tx * 2];
        #pragma unroll
        for (int u = 0; u < 4; u++) {
            o2[u][0] += p2[u].x * va.x + p2[u].y * vb.x;
            o2[u][1] += p2[u].x * va.y + p2[u].y * vb.y;
        }
    }
    {
        float2 vc = *(float2*)&sv[48 * QS + tx * 2];
        #pragma unroll
        for (int u = 0; u < 4; u++) {
            float p = sd[(ty + u * 16) * DS + 48];
            o2[u][0] += p * vc.x;
            o2[u][1] += p * vc.y;
        }
    }
    #pragma unroll
    for (int u = 0; u < 4; u++) {
        int i = ty + u * 16;
        if (i < WIN2) {
            int ii = i / WIN, jj = i % WIN;
            int m = b * Nn + (wh * WIN + ii) * Wd + (ww * WIN + jj);
            size_t off = (size_t)m * Dd + head * HD + tx * 2;
            *(uint32_t*)(outh + off) = pack_h2(o2[u][0], o2[u][1]);
        }
    }
}

// ================= LN + residual (fp16 stream, fp32 math) =================
__global__ void ln_residual_kernel(const __half* __restrict__ A, const float* __restrict__ g,
                                   const float* __restrict__ be, __half* __restrict__ xh,
                                   int gather) {
    int row = blockIdx.x * 8 + (threadIdx.x >> 5);
    int lane = threadIdx.x & 31;
    int src = row;
    if (gather) {
        int b = row / Nn, rem = row % Nn;
        int h = rem / Wd, w = rem % Wd;
        src = b * Nn + ((h + Hh - DISP) % Hh) * Wd + ((w + Wd - DISP) % Wd);
    }
    uint4 av = ((const uint4*)(A + (size_t)src * Dd))[lane];
    const __half2* hp = (const __half2*)&av;
    float vals[8];
    #pragma unroll
    for (int k = 0; k < 4; k++) {
        float2 f = __half22float2(hp[k]);
        vals[2 * k] = f.x; vals[2 * k + 1] = f.y;
    }
    float s = 0.f, s2 = 0.f;
    #pragma unroll
    for (int k = 0; k < 8; k++) { s += vals[k]; s2 += vals[k] * vals[k]; }
    #pragma unroll
    for (int o = 16; o > 0; o >>= 1) {
        s  += __shfl_xor_sync(~0u, s, o);
        s2 += __shfl_xor_sync(~0u, s2, o);
    }
    float mean = s * (1.f / Dd);
    float var  = s2 * (1.f / Dd) - mean * mean;
    float inv  = rsqrtf(var + EPSLN);

    float4 g0 = ((const float4*)g)[lane * 2],  g1 = ((const float4*)g)[lane * 2 + 1];
    float4 b0 = ((const float4*)be)[lane * 2], b1 = ((const float4*)be)[lane * 2 + 1];

    uint4* xp = (uint4*)(xh + (size_t)row * Dd + lane * 8);
    uint4 xv = *xp;
    const __half2* xh2 = (const __half2*)&xv;
    float r[8];
    #pragma unroll
    for (int k = 0; k < 4; k++) {
        float2 f = __half22float2(xh2[k]);
        r[2 * k] = f.x; r[2 * k + 1] = f.y;
    }
    r[0] += (vals[0] - mean) * inv * g0.x + b0.x;
    r[1] += (vals[1] - mean) * inv * g0.y + b0.y;
    r[2] += (vals[2] - mean) * inv * g0.z + b0.z;
    r[3] += (vals[3] - mean) * inv * g0.w + b0.w;
    r[4] += (vals[4] - mean) * inv * g1.x + b1.x;
    r[5] += (vals[5] - mean) * inv * g1.y + b1.y;
    r[6] += (vals[6] - mean) * inv * g1.z + b1.z;
    r[7] += (vals[7] - mean) * inv * g1.w + b1.w;
    uint4 ov;
    ov.x = pack_h2(r[0], r[1]); ov.y = pack_h2(r[2], r[3]);
    ov.z = pack_h2(r[4], r[5]); ov.w = pack_h2(r[6], r[7]);
    *xp = ov;
}

// ================= final LN (reads fp16 stream) =================
__global__ void ln_final_kernel(const __half* __restrict__ A, const float* __restrict__ g,
                                const float* __restrict__ be, float* __restrict__ out) {
    int row = blockIdx.x * 8 + (threadIdx.x >> 5);
    int lane = threadIdx.x & 31;
    uint4 av = ((const uint4*)(A + (size_t)row * Dd))[lane];
    const __half2* hp = (const __half2*)&av;
    float vals[8];
    #pragma unroll
    for (int k = 0; k < 4; k++) {
        float2 f = __half22float2(hp[k]);
        vals[2 * k] = f.x; vals[2 * k + 1] = f.y;
    }
    float s = 0.f, s2 = 0.f;
    #pragma unroll
    for (int k = 0; k < 8; k++) { s += vals[k]; s2 += vals[k] * vals[k]; }
    #pragma unroll
    for (int o = 16; o > 0; o >>= 1) {
        s  += __shfl_xor_sync(~0u, s, o);
        s2 += __shfl_xor_sync(~0u, s2, o);
    }
    float mean = s * (1.f / Dd);
    float var  = s2 * (1.f / Dd) - mean * mean;
    float inv  = rsqrtf(var + EPSLN);
    float4 g0 = ((const float4*)g)[lane * 2],  g1 = ((const float4*)g)[lane * 2 + 1];
    float4 b0 = ((const float4*)be)[lane * 2], b1 = ((const float4*)be)[lane * 2 + 1];
    float4 o0, o1;
    o0.x = (vals[0] - mean) * inv * g0.x + b0.x;
    o0.y = (vals[1] - mean) * inv * g0.y + b0.y;
    o0.z = (vals[2] - mean) * inv * g0.z + b0.z;
    o0.w = (vals[3] - mean) * inv * g0.w + b0.w;
    o1.x = (vals[4] - mean) * inv * g1.x + b1.x;
    o1.y = (vals[5] - mean) * inv * g1.y + b1.y;
    o1.z = (vals[6] - mean) * inv * g1.z + b1.z;
    o1.w = (vals[7] - mean) * inv * g1.w + b1.w;
    float4* out4 = (float4*)(out + (size_t)row * Dd + lane * 8);
    out4[0] = o0; out4[1] = o1;
}

// ================= launch =================
extern "C" void kernel_launch(void* const* d_in, const int* in_sizes, int n_in,
                              void* d_out, int out_size) {
    const float* x    = (const float*)d_in[0];
    const float* spe  = (const float*)d_in[1];
    const float* qkvw = (const float*)d_in[2];
    const float* tau  = (const float*)d_in[3];
    const float* cw1  = (const float*)d_in[4];
    const float* cb1  = (const float*)d_in[5];
    const float* cw2  = (const float*)d_in[6];
    const float* cb2  = (const float*)d_in[7];
    const float* ow   = (const float*)d_in[8];
    const float* ob   = (const float*)d_in[9];
    const float* ln1g = (const float*)d_in[10];
    const float* ln1b = (const float*)d_in[11];
    const float* fw1  = (const float*)d_in[12];
    const float* fb1  = (const float*)d_in[13];
    const float* fw2  = (const float*)d_in[14];
    const float* fb2  = (const float*)d_in[15];
    const float* ln2g = (const float*)d_in[16];
    const float* ln2b = (const float*)d_in[17];
    const float* ng   = (const float*)d_in[18];
    const float* nb   = (const float*)d_in[19];
    float* out = (float*)d_out;

    float *cpb;
    __half *xmh, *qkv, *ath, *ffh, *tmph, *wth;
    cudaGetSymbolAddress((void**)&cpb,  g_cpb);
    cudaGetSymbolAddress((void**)&xmh,  g_xmh);
    cudaGetSymbolAddress((void**)&qkv,  g_qkv);
    cudaGetSymbolAddress((void**)&ath,  g_ath);
    cudaGetSymbolAddress((void**)&ffh,  g_ffh);
    cudaGetSymbolAddress((void**)&tmph, g_tmp);
    cudaGetSymbolAddress((void**)&wth,  g_wth);

    cudaFuncSetAttribute(hgemm_persist_kernel<0, false>, cudaFuncAttributeMaxDynamicSharedMemorySize, PGEMM_SMEM);
    cudaFuncSetAttribute(hgemm_persist_kernel<0, true>,  cudaFuncAttributeMaxDynamicSharedMemorySize, PGEMM_SMEM);
    cudaFuncSetAttribute(hgemm_persist_kernel<1, false>, cudaFuncAttributeMaxDynamicSharedMemorySize, PGEMM_SMEM);
    cudaFuncSetAttribute(hgemm_kernel<0>, cudaFuncAttributeMaxDynamicSharedMemorySize, GEMM_SMEM);

    // weight transpose + fp16 round, both layers batched via z
    wtconv_kernel<<<dim3(24, 8, 2), dim3(32, 8)>>>(qkvw, wth,          256, 768,
                                                   (size_t)Dd * 768, WLSTRIDE);
    wtconv_kernel<<<dim3(8,  8, 2), dim3(32, 8)>>>(ow,   wth + 196608, 256, 256,
                                                   (size_t)Dd * Dd,  WLSTRIDE);
    wtconv_kernel<<<dim3(32, 8, 2), dim3(32, 8)>>>(fw1,  wth + 262144, 256, 1024,
                                                   (size_t)Dd * FF,  WLSTRIDE);
    wtconv_kernel<<<dim3(8, 32, 2), dim3(32, 8)>>>(fw2,  wth + 524288, 1024, 256,
                                                   (size_t)FF * Dd,  WLSTRIDE);

    // xm = x + spe -> fp16 stream
    {
        int n4 = MROWS * Dd / 4;
        add_spe_kernel<<<(n4 + 255) / 256, 256>>>(x, spe, xmh, n4);
    }

    const int lnBlocks = MROWS / 8;
    for (int layer = 0; layer < 2; layer++) {
        int shifted = (layer == 1);
        size_t wo = (size_t)layer * WLSTRIDE;

        cpb_kernel<<<WIN2 * WIN2, 256>>>(cw1 + layer * 2 * CPBH, cb1 + layer * CPBH,
                                         cw2 + layer * CPBH * HEADS, cb2 + layer * HEADS, cpb);

        // qkv = (rolled) xm @ qkv_w -> fp16   (persistent, 6 x 24 = 144 CTAs)
        if (shifted)
            hgemm_persist_kernel<0, true><<<dim3(6, 24), 256, PGEMM_SMEM>>>(
                xmh, wth + wo, nullptr, qkv, 768, 24);
        else
            hgemm_persist_kernel<0, false><<<dim3(6, 24), 256, PGEMM_SMEM>>>(
                xmh, wth + wo, nullptr, qkv, 768, 24);

        attn_kernel<<<dim3(NW, HEADS, Bb), 256>>>(qkv, tau + layer * HEADS, cpb, ath, shifted);

        // o-proj -> tmp (fp16)   (persistent, 2 x 74 = 148 CTAs)
        hgemm_persist_kernel<0, false><<<dim3(2, 74), 256, PGEMM_SMEM>>>(
            ath, wth + wo + 196608, ob + layer * Dd, tmph, 256, 74);

        // xm += LN(oproj) (rolled back if shifted)
        ln_residual_kernel<<<lnBlocks, 256>>>(tmph, ln1g + layer * Dd, ln1b + layer * Dd,
                                              xmh, shifted);

        // ffn1: gelu(xm @ fw1 + fb1) -> fp16   (persistent, 8 x 18 = 144 CTAs)
        hgemm_persist_kernel<1, false><<<dim3(8, 18), 256, PGEMM_SMEM>>>(
            xmh, wth + wo + 262144, fb1 + layer * FF, ffh, 1024, 18);

        // ffn2 -> tmp (fp16)   (streaming, K=1024, BK=64)
        hgemm_kernel<0><<<dim3(2, MROWS / 256), 256, GEMM_SMEM>>>(
            ffh, wth + wo + 524288, fb2 + layer * Dd, tmph, 256, 1024);

        // xm += LN(ffn2)
        ln_residual_kernel<<<lnBlocks, 256>>>(tmph, ln2g + layer * Dd, ln2b + layer * Dd,
                                              xmh, 0);
    }

    ln_final_kernel<<<MROWS / 8, 256>>>(xmh, ng, nb, out);
}

// round 17
// speedup vs baseline: 1.2776x; 1.0650x over previous
#include <cuda_runtime.h>
#include <cuda_fp16.h>
#include <cstdint>
#include <math.h>

#define Bb     16
#define Hh     56
#define Wd     56
#define Nn     3136
#define Dd     256
#define HEADS  8
#define HD     32
#define WIN    7
#define WIN2   49
#define NWH    8
#define NW     64
#define DISP   3
#define FF     1024
#define CPBH   512
#define EPSLN  1e-5f
#define MROWS  50176   // B * N
#define MTILES 196     // MROWS / 256

// ================= PTX helpers =================
__device__ __forceinline__ uint32_t smem_to_u32(const void* p) {
    uint32_t a;
    asm("{ .reg .u64 t; cvta.to.shared.u64 t, %1; cvt.u32.u64 %0, t; }" : "=r"(a) : "l"(p));
    return a;
}
#define CP_ASYNC_CG(dst, src) \
    asm volatile("cp.async.cg.shared.global [%0], [%1], 16;" :: "r"(dst), "l"(src))
#define CP_ASYNC_COMMIT() asm volatile("cp.async.commit_group;" ::: "memory")
#define CP_ASYNC_WAIT(n)  asm volatile("cp.async.wait_group %0;" :: "n"(n) : "memory")

__device__ __forceinline__ void ldsm_x4(uint32_t* r, uint32_t addr) {
    asm volatile("ldmatrix.sync.aligned.m8n8.x4.shared.b16 {%0,%1,%2,%3}, [%4];"
        : "=r"(r[0]), "=r"(r[1]), "=r"(r[2]), "=r"(r[3]) : "r"(addr));
}
__device__ __forceinline__ void ldsm_x4_t(uint32_t* r, uint32_t addr) {
    asm volatile("ldmatrix.sync.aligned.m8n8.x4.trans.shared.b16 {%0,%1,%2,%3}, [%4];"
        : "=r"(r[0]), "=r"(r[1]), "=r"(r[2]), "=r"(r[3]) : "r"(addr));
}
__device__ __forceinline__ void mma_f16(float* c, const uint32_t* a, const uint32_t* b) {
    asm volatile("mma.sync.aligned.m16n8k16.row.col.f32.f16.f16.f32 "
        "{%0,%1,%2,%3},{%4,%5,%6,%7},{%8,%9},{%0,%1,%2,%3};"
        : "+f"(c[0]), "+f"(c[1]), "+f"(c[2]), "+f"(c[3])
        : "r"(a[0]), "r"(a[1]), "r"(a[2]), "r"(a[3]), "r"(b[0]), "r"(b[1]));
}

// ================= device scratch =================
__device__ __half g_xmh [MROWS * Dd];          // fp16 residual stream
__device__ __half g_qkv [MROWS * 3 * Dd];
__device__ __half g_ath [MROWS * Dd];
__device__ __half g_ffh [MROWS * FF];
__device__ __half g_tmp [MROWS * Dd];
__device__ float  g_cpb [HEADS * WIN2 * WIN2];
// transposed fp16 weights, per layer:
// [0) qkvT 768x256 | 196608) owT 256x256 | 262144) fw1T 1024x256 | 524288) fw2T 256x1024
#define WLSTRIDE 786432
__device__ __half g_wth [2 * WLSTRIDE];

// ================= small helpers =================
__device__ __forceinline__ uint32_t pack_h2(float a, float b) {
    __half2 h = __floats2half2_rn(a, b);
    return *(uint32_t*)&h;
}

// ================= add SPE (fp16 out) =================
__global__ void add_spe_kernel(const float* __restrict__ x, const float* __restrict__ spe,
                               __half* __restrict__ xh, int n4) {
    int i = blockIdx.x * blockDim.x + threadIdx.x;
    if (i < n4) {
        float4 a = ((const float4*)x)[i];
        float4 b = ((const float4*)spe)[i];
        uint2 h;
        h.x = pack_h2(a.x + b.x, a.y + b.y);
        h.y = pack_h2(a.z + b.z, a.w + b.w);
        ((uint2*)xh)[i] = h;
    }
}

// ================= weight transpose + fp16 round: W[K,N] -> T[N,K], z = layer =================
__global__ void wtconv_kernel(const float* __restrict__ W, __half* __restrict__ Th,
                              int K, int N, size_t wstride, size_t tstride) {
    W  += (size_t)blockIdx.z * wstride;
    Th += (size_t)blockIdx.z * tstride;
    __shared__ float t[32][33];
    int bn = blockIdx.x * 32, bk = blockIdx.y * 32;
    int tx = threadIdx.x, ty = threadIdx.y;
    #pragma unroll
    for (int j = 0; j < 32; j += 8)
        t[ty + j][tx] = W[(size_t)(bk + ty + j) * N + bn + tx];
    __syncthreads();
    #pragma unroll
    for (int j = 0; j < 32; j += 8) {
        Th[(size_t)(bn + ty + j) * K + bk + tx] = __float2half_rn(t[tx][ty + j]);
    }
}

// ================= CPB MLP =================
__global__ void cpb_kernel(const float* __restrict__ cw1, const float* __restrict__ cb1,
                           const float* __restrict__ cw2, const float* __restrict__ cb2,
                           float* __restrict__ cpb) {
    int p = blockIdx.x;
    int i = p / WIN2, j = p % WIN2;
    float dy = (float)(j / WIN - i / WIN);
    float dx = (float)(j % WIN - i % WIN);
    float r0 = ((dy > 0.f) - (dy < 0.f)) * log1pf(fabsf(dy));
    float r1 = ((dx > 0.f) - (dx < 0.f)) * log1pf(fabsf(dx));
    int tid = threadIdx.x;
    int c0 = tid, c1 = tid + 256;
    float h0 = fmaxf(r0 * cw1[c0] + r1 * cw1[CPBH + c0] + cb1[c0], 0.f);
    float h1 = fmaxf(r0 * cw1[c1] + r1 * cw1[CPBH + c1] + cb1[c1], 0.f);
    __shared__ float red[256];
    for (int h = 0; h < HEADS; h++) {
        red[tid] = h0 * cw2[c0 * HEADS + h] + h1 * cw2[c1 * HEADS + h];
        __syncthreads();
        for (int s = 128; s > 0; s >>= 1) {
            if (tid < s) red[tid] += red[tid + s];
            __syncthreads();
        }
        if (tid == 0) cpb[h * (WIN2 * WIN2) + p] = red[0] + cb2[h];
        __syncthreads();
    }
}

// ================= shared epilogue (fp16 out only) =================
template<int ACT>
__device__ __forceinline__ void gemm_epilogue(
    float acc[4][8][4], int bm, int bn, int warpM, int warpN, int lane,
    const float* __restrict__ bias, __half* __restrict__ Ch, int Ntot) {
    const int g = lane >> 2, q = lane & 3;
    #pragma unroll
    for (int m = 0; m < 4; m++) {
        #pragma unroll
        for (int n = 0; n < 8; n++) {
            int col = bn + warpN * 64 + n * 8 + 2 * q;
            float b0 = bias ? bias[col] : 0.f;
            float b1 = bias ? bias[col + 1] : 0.f;
            #pragma unroll
            for (int hrow = 0; hrow < 2; hrow++) {
                int row = bm + warpM * 64 + m * 16 + g + hrow * 8;
                float v0 = acc[m][n][hrow * 2 + 0] + b0;
                float v1 = acc[m][n][hrow * 2 + 1] + b1;
                if (ACT == 1) {
                    v0 = v0 * 0.5f * (1.f + erff(v0 * 0.7071067811865476f));
                    v1 = v1 * 0.5f * (1.f + erff(v1 * 0.7071067811865476f));
                }
                *(uint32_t*)(Ch + (size_t)row * Ntot + col) = pack_h2(v0, v1);
            }
        }
    }
}

// ================= persistent-B HMMA GEMM, K = 256 fixed, BK = 64 =================
#define SAS2     72                          // padded A row stride (halves), 144B
#define PA_STAGE (256 * SAS2 * 2)            // 36864
#define PSTAGES  3
#define PB_STRIDE 264
#define PB_BYTES (128 * PB_STRIDE * 2)       // 67584
#define PGEMM_SMEM (PB_BYTES + PSTAGES * PA_STAGE)  // 178176

template<int ACT, bool GATHER>
__global__ void __launch_bounds__(256, 1)
hgemm_persist_kernel(const __half* __restrict__ Ah, const __half* __restrict__ Bth,
                     const float* __restrict__ bias, __half* __restrict__ Ch,
                     int Ntot, int G) {
    extern __shared__ char smem_raw[];
    const uint32_t sB = smem_to_u32(smem_raw);
    const uint32_t sA = sB + PB_BYTES;
    const int tid  = threadIdx.x;
    const int lane = tid & 31, wid = tid >> 5;
    const int warpM = wid >> 1, warpN = wid & 1;
    const int bn = blockIdx.x * 128;
    const int g  = blockIdx.y;

    #pragma unroll
    for (int it = 0; it < 16; it++) {
        int idx = tid + it * 256;
        int n = idx >> 5, q = idx & 31;
        CP_ASYNC_CG(sB + (uint32_t)(n * (PB_STRIDE * 2) + q * 16),
                    Bth + (size_t)(bn + n) * 256 + q * 8);
    }
    CP_ASYNC_COMMIT();

    int arow_s[8], acol_s[8];
    uint32_t aoff[8];
    #pragma unroll
    for (int l = 0; l < 8; l++) {
        int c = tid + l * 256;
        int r = c >> 3, q = c & 7;
        arow_s[l] = r; acol_s[l] = q * 8;
        aoff[l] = (uint32_t)(r * (SAS2 * 2) + q * 16);
    }

    const int ntl = (MTILES - 1 - g) / G + 1;
    const int total_cc = ntl * 4;

    auto issue = [&](int cc, int stg_i) {
        int tile = cc >> 2, c = cc & 3;
        int bm = (g + tile * G) * 256;
        uint32_t stg = sA + (uint32_t)stg_i * PA_STAGE;
        int kt = c << 6;
        #pragma unroll
        for (int l = 0; l < 8; l++) {
            int gm = bm + arow_s[l];
            if (GATHER) {
                int b = gm / Nn, rem = gm - b * Nn;
                int h = rem / Wd, w = rem - h * Wd;
                h = (h + DISP) % Hh; w = (w + DISP) % Wd;
                gm = b * Nn + h * Wd + w;
            }
            CP_ASYNC_CG(stg + aoff[l], Ah + (size_t)gm * 256 + kt + acol_s[l]);
        }
    };

    float acc[4][8][4];
    #pragma unroll
    for (int m = 0; m < 4; m++)
        #pragma unroll
        for (int n = 0; n < 8; n++)
            #pragma unroll
            for (int e = 0; e < 4; e++) acc[m][n][e] = 0.f;

    const int arow  = (lane & 15);
    const int ahalf = (lane >> 4);
    const int bidx  = lane & 7;
    const int bkh   = (lane >> 3) & 1;
    const int bsub  = lane >> 4;

    issue(0, 0); CP_ASYNC_COMMIT();
    if (total_cc > 1) issue(1, 1);
    CP_ASYNC_COMMIT();

    int sc = 0, scn = 2;
    for (int cc = 0; cc < total_cc; cc++) {
        CP_ASYNC_WAIT(1);
        __syncthreads();
        if (cc + 2 < total_cc) issue(cc + 2, scn);
        CP_ASYNC_COMMIT();

        uint32_t stg = sA + (uint32_t)sc * PA_STAGE;
        const int c = cc & 3;
        #pragma unroll
        for (int ks = 0; ks < 4; ks++) {
            const int kg = c * 4 + ks;
            uint32_t ah[4][4], bh[8][2];
            #pragma unroll
            for (int m = 0; m < 4; m++) {
                uint32_t off = (uint32_t)((warpM * 64 + m * 16 + arow) * (SAS2 * 2)
                                          + (ks * 16 + ahalf * 8) * 2);
                ldsm_x4(ah[m], stg + off);
            }
            #pragma unroll
            for (int pr = 0; pr < 4; pr++) {
                uint32_t off = (uint32_t)((warpN * 64 + pr * 16 + bsub * 8 + bidx) * (PB_STRIDE * 2)
                                          + (kg * 16 + bkh * 8) * 2);
                uint32_t t[4];
                ldsm_x4(t, sB + off);
                bh[pr * 2][0] = t[0]; bh[pr * 2][1] = t[1];
                bh[pr * 2 + 1][0] = t[2]; bh[pr * 2 + 1][1] = t[3];
            }
            #pragma unroll
            for (int m = 0; m < 4; m++)
                #pragma unroll
                for (int n = 0; n < 8; n++) mma_f16(acc[m][n], ah[m], bh[n]);
        }
        sc = (sc == 2) ? 0 : sc + 1;
        scn = (scn == 2) ? 0 : scn + 1;

        if (c == 3) {
            int bm = (g + (cc >> 2) * G) * 256;
            gemm_epilogue<ACT>(acc, bm, bn, warpM, warpN, lane, bias, Ch, Ntot);
            #pragma unroll
            for (int m = 0; m < 4; m++)
                #pragma unroll
                for (int n = 0; n < 8; n++)
                    #pragma unroll
                    for (int e = 0; e < 4; e++) acc[m][n][e] = 0.f;
        }
    }
}

// ================= streaming HMMA GEMM (K=1024 ffn2), BK = 64 =================
#define SB_OFF   (256 * SAS2 * 2)            // 36864 (A part)
#define STAGE_B2 (SB_OFF + 128 * SAS2 * 2)   // 55296
#define GEMM_SMEM (3 * STAGE_B2)             // 165888

template<int ACT>
__global__ void __launch_bounds__(256, 1)
hgemm_kernel(const __half* __restrict__ Ah, const __half* __restrict__ Bth,
             const float* __restrict__ bias, __half* __restrict__ Ch,
             int Ntot, int K) {
    extern __shared__ char smem_raw[];
    const uint32_t sbase = smem_to_u32(smem_raw);
    const int tid  = threadIdx.x;
    const int lane = tid & 31, wid = tid >> 5;
    const int warpM = wid >> 1, warpN = wid & 1;
    const int bm = blockIdx.y * 256, bn = blockIdx.x * 128;

    const __half *pAh[8], *pBh[4];
    uint32_t aoff[8], boff[4];
    #pragma unroll
    for (int l = 0; l < 8; l++) {
        int c = tid + l * 256;
        int r = c >> 3, q = c & 7;
        pAh[l] = Ah + (size_t)(bm + r) * K + q * 8;
        aoff[l] = (uint32_t)(r * (SAS2 * 2) + q * 16);
    }
    #pragma unroll
    for (int l = 0; l < 4; l++) {
        int c = tid + l * 256;
        int r = c >> 3, q = c & 7;
        pBh[l] = Bth + (size_t)(bn + r) * K + q * 8;
        boff[l] = (uint32_t)(r * (SAS2 * 2) + q * 16);
    }

    float acc[4][8][4];
    #pragma unroll
    for (int m = 0; m < 4; m++)
        #pragma unroll
        for (int n = 0; n < 8; n++)
            #pragma unroll
            for (int e = 0; e < 4; e++) acc[m][n][e] = 0.f;

    const int nch = K >> 6;

    auto load_stage = [&](int c, int stg_i) {
        uint32_t stg = sbase + (uint32_t)stg_i * STAGE_B2;
        int kt = c << 6;
        #pragma unroll
        for (int l = 0; l < 8; l++)
            CP_ASYNC_CG(stg + aoff[l], pAh[l] + kt);
        #pragma unroll
        for (int l = 0; l < 4; l++)
            CP_ASYNC_CG(stg + SB_OFF + boff[l], pBh[l] + kt);
    };

    const int arow  = (lane & 15);
    const int ahalf = (lane >> 4);
    const int bidx  = lane & 7;
    const int bkh   = (lane >> 3) & 1;
    const int bsub  = lane >> 4;

    load_stage(0, 0); CP_ASYNC_COMMIT();
    if (nch > 1) load_stage(1, 1);
    CP_ASYNC_COMMIT();

    int sc = 0, scn = 2;
    for (int c = 0; c < nch; c++) {
        CP_ASYNC_WAIT(1);
        __syncthreads();
        if (c + 2 < nch) load_stage(c + 2, scn);
        CP_ASYNC_COMMIT();

        uint32_t stg = sbase + (uint32_t)sc * STAGE_B2;
        #pragma unroll
        for (int ks = 0; ks < 4; ks++) {
            uint32_t ah[4][4], bh[8][2];
            #pragma unroll
            for (int m = 0; m < 4; m++) {
                uint32_t off = (uint32_t)((warpM * 64 + m * 16 + arow) * (SAS2 * 2)
                                          + (ks * 16 + ahalf * 8) * 2);
                ldsm_x4(ah[m], stg + off);
            }
            #pragma unroll
            for (int pr = 0; pr < 4; pr++) {
                uint32_t off = (uint32_t)((warpN * 64 + pr * 16 + bsub * 8 + bidx) * (SAS2 * 2)
                                          + (ks * 16 + bkh * 8) * 2);
                uint32_t t[4];
                ldsm_x4(t, stg + SB_OFF + off);
                bh[pr * 2][0] = t[0]; bh[pr * 2][1] = t[1];
                bh[pr * 2 + 1][0] = t[2]; bh[pr * 2 + 1][1] = t[3];
            }
            #pragma unroll
            for (int m = 0; m < 4; m++)
                #pragma unroll
                for (int n = 0; n < 8; n++) mma_f16(acc[m][n], ah[m], bh[n]);
        }
        sc = (sc == 2) ? 0 : sc + 1;
        scn = (scn == 2) ? 0 : scn + 1;
    }

    gemm_epilogue<ACT>(acc, bm, bn, warpM, warpN, lane, bias, Ch, Ntot);
}

// ================= window attention: HMMA QK^T + HMMA AV =================
#define QSH 40            // fp16 q/k/v row stride (halves), 80B
#define PSH 72            // fp16 prob row stride (halves), 144B
#define DS  52
__global__ void __launch_bounds__(256, 6)
attn_kernel(const __half* __restrict__ qkv, const float* __restrict__ tau,
            const float* __restrict__ cpb, __half* __restrict__ outh, int shifted) {
    __shared__ __half sqh[64 * QSH];
    __shared__ __half skh[64 * QSH];
    __shared__ __half svh[64 * QSH];
    __shared__ float  sd [64 * DS];
    __shared__ __half sp [64 * PSH];

    const int wi   = blockIdx.x;
    const int head = blockIdx.y;
    const int b    = blockIdx.z;
    const int wh = wi >> 3, ww = wi & 7;
    const int tid = threadIdx.x;

    // load: q,k,v verbatim fp16
    for (int e = tid; e < WIN2 * 12; e += 256) {
        int t = e / (WIN2 * 4);
        int rem = e - t * (WIN2 * 4);
        int r = rem >> 2, c = rem & 3;
        int i = r / WIN, j = r % WIN;
        int m = b * Nn + (wh * WIN + i) * Wd + (ww * WIN + j);
        uint4 u = *(const uint4*)(qkv + (size_t)m * 768 + t * 256 + head * HD + c * 8);
        __half* dst = (t == 0 ? sqh : (t == 1 ? skh : svh)) + r * QSH + c * 8;
        *(uint2*)(dst)     = make_uint2(u.x, u.y);
        *(uint2*)(dst + 4) = make_uint2(u.z, u.w);
    }
    // zero-pad rows 49..63 of q,k,v (3 x 15 rows x 8 uint2 = 360)
    for (int e = tid; e < 360; e += 256) {
        int t = e / 120;
        int e2 = e - t * 120;
        int r = WIN2 + (e2 >> 3), d = (e2 & 7) * 4;
        __half* base = (t == 0 ? sqh : (t == 1 ? skh : svh));
        *(uint2*)(base + r * QSH + d) = make_uint2(0u, 0u);
    }
    __syncthreads();

    // l2-normalize rows of q,k (fp32 math, fp16 store)
    for (int t = tid; t < 2 * WIN2; t += 256) {
        __half* row = (t < WIN2) ? (sqh + t * QSH) : (skh + (t - WIN2) * QSH);
        float s = 0.f;
        #pragma unroll
        for (int d = 0; d < HD; d += 2) {
            float2 v = __half22float2(*(__half2*)(row + d));
            s += v.x * v.x + v.y * v.y;
        }
        float inv = 1.f / fmaxf(sqrtf(s), 1e-12f);
        #pragma unroll
        for (int d = 0; d < HD; d += 2) {
            float2 v = __half22float2(*(__half2*)(row + d));
            *(uint32_t*)(row + d) = pack_h2(v.x * inv, v.y * inv);
        }
    }
    __syncthreads();

    const float tscale = 1.f / fmaxf(tau[head], 0.01f);
    const int lane = tid & 31, wid = tid >> 5;

    // ---- QK^T via HMMA ----
    {
        const int mrow  = wid & 3, nhalf = wid >> 2;
        const int arow  = lane & 15, ahalf = lane >> 4;
        const int bidx  = lane & 7, bkh = (lane >> 3) & 1, bsub = lane >> 4;
        const uint32_t sq_u = smem_to_u32(sqh);
        const uint32_t sk_u = smem_to_u32(skh);

        float dacc[4][4];
        #pragma unroll
        for (int nt = 0; nt < 4; nt++)
            #pragma unroll
            for (int e = 0; e < 4; e++) dacc[nt][e] = 0.f;

        #pragma unroll
        for (int ks = 0; ks < 2; ks++) {
            uint32_t a[4], bh[4][2];
            ldsm_x4(a, sq_u + (uint32_t)(((mrow * 16 + arow) * QSH
                                          + ks * 16 + ahalf * 8) * 2));
            #pragma unroll
            for (int pr = 0; pr < 2; pr++) {
                uint32_t t4[4];
                ldsm_x4(t4, sk_u + (uint32_t)(((nhalf * 32 + pr * 16 + bsub * 8 + bidx) * QSH
                                               + ks * 16 + bkh * 8) * 2));
                bh[pr * 2][0] = t4[0]; bh[pr * 2][1] = t4[1];
                bh[pr * 2 + 1][0] = t4[2]; bh[pr * 2 + 1][1] = t4[3];
            }
            #pragma unroll
            for (int nt = 0; nt < 4; nt++) mma_f16(dacc[nt], a, bh[nt]);
        }

        const int g = lane >> 2, q = lane & 3;
        #pragma unroll
        for (int hrow = 0; hrow < 2; hrow++) {
            int i = mrow * 16 + g + hrow * 8;
            if (i < WIN2) {
                #pragma unroll
                for (int nt = 0; nt < 4; nt++) {
                    #pragma unroll
                    for (int e = 0; e < 2; e++) {
                        int j = nhalf * 32 + nt * 8 + 2 * q + e;
                        if (j >= WIN2) continue;
                        float val = dacc[nt][hrow * 2 + e] * tscale
                                  + cpb[head * (WIN2 * WIN2) + i * WIN2 + j];
                        if (shifted) {
                            if (wh == NWH - 1 && ((i >= 28) != (j >= 28))) val = -1e30f;
                            if (ww == NWH - 1 && (((i % WIN) >= 4) != ((j % WIN) >= 4))) val = -1e30f;
                        }
                        sd[i * DS + j] = val;
                    }
                }
            }
        }
    }
    __syncthreads();

    // softmax (one warp per row) -> fp16 probs in sp, zero-padded j >= 49
    for (int r = wid; r < WIN2; r += 8) {
        float v0 = sd[r * DS + lane];
        float v1 = (lane + 32 < WIN2) ? sd[r * DS + lane + 32] : -3e38f;
        float mx = fmaxf(v0, v1);
        #pragma unroll
        for (int o = 16; o > 0; o >>= 1) mx = fmaxf(mx, __shfl_xor_sync(~0u, mx, o));
        float e0 = __expf(v0 - mx);
        float e1 = (lane + 32 < WIN2) ? __expf(v1 - mx) : 0.f;
        float s = e0 + e1;
        #pragma unroll
        for (int o = 16; o > 0; o >>= 1) s += __shfl_xor_sync(~0u, s, o);
        float inv = 1.f / s;
        sp[r * PSH + lane]      = __float2half_rn(e0 * inv);
        sp[r * PSH + lane + 32] = __float2half_rn(e1 * inv);   // e1=0 when j>=49
    }
    // zero p rows 49..63 (A operand padding; avoids NaN garbage)
    for (int e = tid; e < 15 * 16; e += 256) {
        int r = WIN2 + (e >> 4), d = (e & 15) * 4;
        *(uint2*)(sp + r * PSH + d) = make_uint2(0u, 0u);
    }
    __syncthreads();

    // ---- AV via HMMA: warp = (mrow 0..3) x (nhalf 0..1); out 16x16 per warp ----
    {
        const int mrow  = wid & 3, nhalf = wid >> 2;
        const int arow  = lane & 15, ahalf = lane >> 4;
        const uint32_t sp_u = smem_to_u32(sp);
        const uint32_t sv_u = smem_to_u32(svh);
        const int brow = (lane & 7) + ((lane >> 3) & 1) * 8;
        const int bcol = nhalf * 16 + (lane >> 4) * 8;

        float oacc[2][4];
        #pragma unroll
        for (int nt = 0; nt < 2; nt++)
            #pragma unroll
            for (int e = 0; e < 4; e++) oacc[nt][e] = 0.f;

        #pragma unroll
        for (int ks = 0; ks < 4; ks++) {
            uint32_t a[4], t4[4];
            ldsm_x4(a, sp_u + (uint32_t)(((mrow * 16 + arow) * PSH
                                          + ks * 16 + ahalf * 8) * 2));
            ldsm_x4_t(t4, sv_u + (uint32_t)(((ks * 16 + brow) * QSH + bcol) * 2));
            uint32_t b0[2] = { t4[0], t4[1] };
            uint32_t b1[2] = { t4[2], t4[3] };
            mma_f16(oacc[0], a, b0);
            mma_f16(oacc[1], a, b1);
        }

        const int g = lane >> 2, q = lane & 3;
        #pragma unroll
        for (int hrow = 0; hrow < 2; hrow++) {
            int i = mrow * 16 + g + hrow * 8;
            if (i < WIN2) {
                int ii = i / WIN, jj = i % WIN;
                int m = b * Nn + (wh * WIN + ii) * Wd + (ww * WIN + jj);
                size_t base = (size_t)m * Dd + head * HD;
                #pragma unroll
                for (int nt = 0; nt < 2; nt++) {
                    int col = nhalf * 16 + nt * 8 + 2 * q;
                    *(uint32_t*)(outh + base + col) =
                        pack_h2(oacc[nt][hrow * 2], oacc[nt][hrow * 2 + 1]);
                }
            }
        }
    }
}

// ================= LN + residual (fp16 stream, fp32 math) =================
__global__ void ln_residual_kernel(const __half* __restrict__ A, const float* __restrict__ g,
                                   const float* __restrict__ be, __half* __restrict__ xh,
                                   int gather) {
    int row = blockIdx.x * 8 + (threadIdx.x >> 5);
    int lane = threadIdx.x & 31;
    int src = row;
    if (gather) {
        int b = row / Nn, rem = row % Nn;
        int h = rem / Wd, w = rem % Wd;
        src = b * Nn + ((h + Hh - DISP) % Hh) * Wd + ((w + Wd - DISP) % Wd);
    }
    uint4 av = ((const uint4*)(A + (size_t)src * Dd))[lane];
    const __half2* hp = (const __half2*)&av;
    float vals[8];
    #pragma unroll
    for (int k = 0; k < 4; k++) {
        float2 f = __half22float2(hp[k]);
        vals[2 * k] = f.x; vals[2 * k + 1] = f.y;
    }
    float s = 0.f, s2 = 0.f;
    #pragma unroll
    for (int k = 0; k < 8; k++) { s += vals[k]; s2 += vals[k] * vals[k]; }
    #pragma unroll
    for (int o = 16; o > 0; o >>= 1) {
        s  += __shfl_xor_sync(~0u, s, o);
        s2 += __shfl_xor_sync(~0u, s2, o);
    }
    float mean = s * (1.f / Dd);
    float var  = s2 * (1.f / Dd) - mean * mean;
    float inv  = rsqrtf(var + EPSLN);

    float4 g0 = ((const float4*)g)[lane * 2],  g1 = ((const float4*)g)[lane * 2 + 1];
    float4 b0 = ((const float4*)be)[lane * 2], b1 = ((const float4*)be)[lane * 2 + 1];

    uint4* xp = (uint4*)(xh + (size_t)row * Dd + lane * 8);
    uint4 xv = *xp;
    const __half2* xh2 = (const __half2*)&xv;
    float r[8];
    #pragma unroll
    for (int k = 0; k < 4; k++) {
        float2 f = __half22float2(xh2[k]);
        r[2 * k] = f.x; r[2 * k + 1] = f.y;
    }
    r[0] += (vals[0] - mean) * inv * g0.x + b0.x;
    r[1] += (vals[1] - mean) * inv * g0.y + b0.y;
    r[2] += (vals[2] - mean) * inv * g0.z + b0.z;
    r[3] += (vals[3] - mean) * inv * g0.w + b0.w;
    r[4] += (vals[4] - mean) * inv * g1.x + b1.x;
    r[5] += (vals[5] - mean) * inv * g1.y + b1.y;
    r[6] += (vals[6] - mean) * inv * g1.z + b1.z;
    r[7] += (vals[7] - mean) * inv * g1.w + b1.w;
    uint4 ov;
    ov.x = pack_h2(r[0], r[1]); ov.y = pack_h2(r[2], r[3]);
    ov.z = pack_h2(r[4], r[5]); ov.w = pack_h2(r[6], r[7]);
    *xp = ov;
}

// ================= final LN (reads fp16 stream) =================
__global__ void ln_final_kernel(const __half* __restrict__ A, const float* __restrict__ g,
                                const float* __restrict__ be, float* __restrict__ out) {
    int row = blockIdx.x * 8 + (threadIdx.x >> 5);
    int lane = threadIdx.x & 31;
    uint4 av = ((const uint4*)(A + (size_t)row * Dd))[lane];
    const __half2* hp = (const __half2*)&av;
    float vals[8];
    #pragma unroll
    for (int k = 0; k < 4; k++) {
        float2 f = __half22float2(hp[k]);
        vals[2 * k] = f.x; vals[2 * k + 1] = f.y;
    }
    float s = 0.f, s2 = 0.f;
    #pragma unroll
    for (int k = 0; k < 8; k++) { s += vals[k]; s2 += vals[k] * vals[k]; }
    #pragma unroll
    for (int o = 16; o > 0; o >>= 1) {
        s  += __shfl_xor_sync(~0u, s, o);
        s2 += __shfl_xor_sync(~0u, s2, o);
    }
    float mean = s * (1.f / Dd);
    float var  = s2 * (1.f / Dd) - mean * mean;
    float inv  = rsqrtf(var + EPSLN);
    float4 g0 = ((const float4*)g)[lane * 2],  g1 = ((const float4*)g)[lane * 2 + 1];
    float4 b0 = ((const float4*)be)[lane * 2], b1 = ((const float4*)be)[lane * 2 + 1];
    float4 o0, o1;
    o0.x = (vals[0] - mean) * inv * g0.x + b0.x;
    o0.y = (vals[1] - mean) * inv * g0.y + b0.y;
    o0.z = (vals[2] - mean) * inv * g0.z + b0.z;
    o0.w = (vals[3] - mean) * inv * g0.w + b0.w;
    o1.x = (vals[4] - mean) * inv * g1.x + b1.x;
    o1.y = (vals[5] - mean) * inv * g1.y + b1.y;
    o1.z = (vals[6] - mean) * inv * g1.z + b1.z;
    o1.w = (vals[7] - mean) * inv * g1.w + b1.w;
    float4* out4 = (float4*)(out + (size_t)row * Dd + lane * 8);
    out4[0] = o0; out4[1] = o1;
}

// ================= launch =================
extern "C" void kernel_launch(void* const* d_in, const int* in_sizes, int n_in,
                              void* d_out, int out_size) {
    const float* x    = (const float*)d_in[0];
    const float* spe  = (const float*)d_in[1];
    const float* qkvw = (const float*)d_in[2];
    const float* tau  = (const float*)d_in[3];
    const float* cw1  = (const float*)d_in[4];
    const float* cb1  = (const float*)d_in[5];
    const float* cw2  = (const float*)d_in[6];
    const float* cb2  = (const float*)d_in[7];
    const float* ow   = (const float*)d_in[8];
    const float* ob   = (const float*)d_in[9];
    const float* ln1g = (const float*)d_in[10];
    const float* ln1b = (const float*)d_in[11];
    const float* fw1  = (const float*)d_in[12];
    const float* fb1  = (const float*)d_in[13];
    const float* fw2  = (const float*)d_in[14];
    const float* fb2  = (const float*)d_in[15];
    const float* ln2g = (const float*)d_in[16];
    const float* ln2b = (const float*)d_in[17];
    const float* ng   = (const float*)d_in[18];
    const float* nb   = (const float*)d_in[19];
    float* out = (float*)d_out;

    float *cpb;
    __half *xmh, *qkv, *ath, *ffh, *tmph, *wth;
    cudaGetSymbolAddress((void**)&cpb,  g_cpb);
    cudaGetSymbolAddress((void**)&xmh,  g_xmh);
    cudaGetSymbolAddress((void**)&qkv,  g_qkv);
    cudaGetSymbolAddress((void**)&ath,  g_ath);
    cudaGetSymbolAddress((void**)&ffh,  g_ffh);
    cudaGetSymbolAddress((void**)&tmph, g_tmp);
    cudaGetSymbolAddress((void**)&wth,  g_wth);

    cudaFuncSetAttribute(hgemm_persist_kernel<0, false>, cudaFuncAttributeMaxDynamicSharedMemorySize, PGEMM_SMEM);
    cudaFuncSetAttribute(hgemm_persist_kernel<0, true>,  cudaFuncAttributeMaxDynamicSharedMemorySize, PGEMM_SMEM);
    cudaFuncSetAttribute(hgemm_persist_kernel<1, false>, cudaFuncAttributeMaxDynamicSharedMemorySize, PGEMM_SMEM);
    cudaFuncSetAttribute(hgemm_kernel<0>, cudaFuncAttributeMaxDynamicSharedMemorySize, GEMM_SMEM);

    // weight transpose + fp16 round, both layers batched via z
    wtconv_kernel<<<dim3(24, 8, 2), dim3(32, 8)>>>(qkvw, wth,          256, 768,
                                                   (size_t)Dd * 768, WLSTRIDE);
    wtconv_kernel<<<dim3(8,  8, 2), dim3(32, 8)>>>(ow,   wth + 196608, 256, 256,
                                                   (size_t)Dd * Dd,  WLSTRIDE);
    wtconv_kernel<<<dim3(32, 8, 2), dim3(32, 8)>>>(fw1,  wth + 262144, 256, 1024,
                                                   (size_t)Dd * FF,  WLSTRIDE);
    wtconv_kernel<<<dim3(8, 32, 2), dim3(32, 8)>>>(fw2,  wth + 524288, 1024, 256,
                                                   (size_t)FF * Dd,  WLSTRIDE);

    // xm = x + spe -> fp16 stream
    {
        int n4 = MROWS * Dd / 4;
        add_spe_kernel<<<(n4 + 255) / 256, 256>>>(x, spe, xmh, n4);
    }

    const int lnBlocks = MROWS / 8;
    for (int layer = 0; layer < 2; layer++) {
        int shifted = (layer == 1);
        size_t wo = (size_t)layer * WLSTRIDE;

        cpb_kernel<<<WIN2 * WIN2, 256>>>(cw1 + layer * 2 * CPBH, cb1 + layer * CPBH,
                                         cw2 + layer * CPBH * HEADS, cb2 + layer * HEADS, cpb);

        // qkv = (rolled) xm @ qkv_w -> fp16   (persistent, 6 x 24 = 144 CTAs)
        if (shifted)
            hgemm_persist_kernel<0, true><<<dim3(6, 24), 256, PGEMM_SMEM>>>(
                xmh, wth + wo, nullptr, qkv, 768, 24);
        else
            hgemm_persist_kernel<0, false><<<dim3(6, 24), 256, PGEMM_SMEM>>>(
                xmh, wth + wo, nullptr, qkv, 768, 24);

        attn_kernel<<<dim3(NW, HEADS, Bb), 256>>>(qkv, tau + layer * HEADS, cpb, ath, shifted);

        // o-proj -> tmp (fp16)   (persistent, 2 x 74 = 148 CTAs)
        hgemm_persist_kernel<0, false><<<dim3(2, 74), 256, PGEMM_SMEM>>>(
            ath, wth + wo + 196608, ob + layer * Dd, tmph, 256, 74);

        // xm += LN(oproj) (rolled back if shifted)
        ln_residual_kernel<<<lnBlocks, 256>>>(tmph, ln1g + layer * Dd, ln1b + layer * Dd,
                                              xmh, shifted);

        // ffn1: gelu(xm @ fw1 + fb1) -> fp16   (persistent, 8 x 18 = 144 CTAs)
        hgemm_persist_kernel<1, false><<<dim3(8, 18), 256, PGEMM_SMEM>>>(
            xmh, wth + wo + 262144, fb1 + layer * FF, ffh, 1024, 18);

        // ffn2 -> tmp (fp16)   (streaming, K=1024, BK=64)
        hgemm_kernel<0><<<dim3(2, MROWS / 256), 256, GEMM_SMEM>>>(
            ffh, wth + wo + 524288, fb2 + layer * Dd, tmph, 256, 1024);

        // xm += LN(ffn2)
        ln_residual_kernel<<<lnBlocks, 256>>>(tmph, ln2g + layer * Dd, ln2b + layer * Dd,
                                              xmh, 0);
    }

    ln_final_kernel<<<MROWS / 8, 256>>>(xmh, ng, nb, out);
}